// round 8
// baseline (speedup 1.0000x reference)
#include <cuda_runtime.h>
#include <cuda_bf16.h>
#include <cstdint>

#define TT 32
#define NN 20000
#define CC 10

// ---------------- SMEM layout (bytes) ----------------
#define WHH_HI 0          /* bf16 [128][128] swizzled */
#define WHH_LO 32768
#define H_HI   65536      /* bf16 [144][128] swizzled (36864 each) */
#define H_LO   102400
#define X_HI   139264     /* Wih staging at init; x_hi; RED/LP overlay in epilogue */
#define X_LO   176128
#define RED_O  139264     /* overlay: float2 [16][144] = 18432 */
#define LP_O   157696     /* overlay: float  [16][144] = 9216  */
#define OUTS_O 65536      /* final overlay over h/x: [16][144][10] f32 = 92160 */
#define RAB_O  212992     /* float [144] (w = e*rstd) */
#define SCAL_O 213568     /* float[2]: S1, S2 */
#define WGS_O  213576     /* float[10] */
#define WB_O   213616     /* float[10] */
#define SMEMSZ 213696

// ---------------------------------------------------------------------------
__device__ __forceinline__ uint32_t smem_u32_of(const void* p) {
    uint32_t a;
    asm("{ .reg .u64 t; cvta.to.shared.u64 t, %1; cvt.u32.u64 %0, t; }" : "=r"(a) : "l"(p));
    return a;
}
__device__ __forceinline__ void mma_bf16(float* c, const uint32_t* a, const uint32_t* b) {
    asm volatile("mma.sync.aligned.m16n8k16.row.col.f32.bf16.bf16.f32 "
        "{%0,%1,%2,%3}, {%4,%5,%6,%7}, {%8,%9}, {%0,%1,%2,%3};"
        : "+f"(c[0]), "+f"(c[1]), "+f"(c[2]), "+f"(c[3])
        : "r"(a[0]), "r"(a[1]), "r"(a[2]), "r"(a[3]), "r"(b[0]), "r"(b[1]));
}
__device__ __forceinline__ void ldsm4(uint32_t* r, uint32_t addr) {
    asm volatile("ldmatrix.sync.aligned.m8n8.x4.shared.b16 {%0,%1,%2,%3}, [%4];"
        : "=r"(r[0]), "=r"(r[1]), "=r"(r[2]), "=r"(r[3]) : "r"(addr));
}
__device__ __forceinline__ void ldsm2(uint32_t* r, uint32_t addr) {
    asm volatile("ldmatrix.sync.aligned.m8n8.x2.shared.b16 {%0,%1}, [%2];"
        : "=r"(r[0]), "=r"(r[1]) : "r"(addr));
}
// swizzled byte offset in a [rows][128] bf16 tile (256 B/row)
__device__ __forceinline__ uint32_t hswz(int r, int k) {
    int k8 = k >> 3;
    int s = (k8 & 8) | ((k8 ^ r) & 7);
    return (uint32_t)(r * 256 + s * 16 + (k & 7) * 2);
}
__device__ __forceinline__ uint32_t packbf(float a, float b) {
    uint32_t p;
    asm("cvt.rn.bf16x2.f32 %0, %1, %2;" : "=r"(p) : "f"(b), "f"(a));
    return p;
}
__device__ __forceinline__ void conv_weight(const float* __restrict__ W,
                                            char* hi, char* lo, int tid, int nthr) {
    for (int idx = tid; idx < 16384; idx += nthr) {
        int r = idx >> 7, k = idx & 127;
        float w = W[idx];
        __nv_bfloat16 wh = __float2bfloat16(w);
        uint32_t o = hswz(r, k);
        *(__nv_bfloat16*)(hi + o) = wh;
        *(__nv_bfloat16*)(lo + o) = __float2bfloat16(w - __bfloat162float(wh));
    }
}

// ===========================================================================
// Single fused kernel: 144 rows/CTA, grid 139 (one wave), 16 warps x n8.
// ===========================================================================
__global__ __launch_bounds__(512, 1) void grn_one(
    const float* __restrict__ X,
    const float* __restrict__ W_ih,  const float* __restrict__ W_hh,
    const float* __restrict__ b_ih,  const float* __restrict__ b_hh,
    const float* __restrict__ ln_g,  const float* __restrict__ ln_b,
    const float* __restrict__ attn_W, const float* __restrict__ attn_b,
    const float* __restrict__ dense_W, const float* __restrict__ dense_b,
    float* __restrict__ out)
{
    extern __shared__ char sm[];
    const uint32_t sb = smem_u32_of(sm);
    const int tid = threadIdx.x, warp = tid >> 5, lane = tid & 31;
    const int g = lane >> 2, q4 = lane & 3;
    const int nw = warp * 8;              // 8 output cols per warp
    const int n0 = blockIdx.x * 144;
    const int cA = nw + q4 * 2;           // thread's 2 cols
    const int ar = lane & 15;
    const int akbase = ((lane >> 4) << 3);
    const int bn = nw + (lane & 7);
    const int bkoff = (((lane >> 3) & 1) << 3);

    // ---- stage weights: Wih -> X region (temp), Whh -> its tiles ----
    conv_weight(W_ih, sm + X_HI, sm + X_LO, tid, 512);
    conv_weight(W_hh, sm + WHH_HI, sm + WHH_LO, tid, 512);
    if (tid == 0) {
        float s1 = 0.f, s2 = 0.f;
        for (int c = 0; c < 128; c++) {
            s1 += attn_W[c] * ln_g[c];
            s2 += attn_W[c] * ln_b[c];
        }
        ((float*)(sm + SCAL_O))[0] = s1;
        ((float*)(sm + SCAL_O))[1] = s2 + attn_b[0];
    }
    if (tid >= 32 && tid < 32 + CC) {
        int c2 = tid - 32;
        float wg = 0.f, wb = 0.f;
        for (int k = 0; k < 128; k++) {
            float wd = dense_W[c2 * 128 + k];
            wg += wd * ln_g[k];
            wb += wd * ln_b[k];
        }
        ((float*)(sm + WGS_O))[c2] = wg;
        ((float*)(sm + WB_O))[c2] = wb;
    }
    __syncthreads();

    // ---- Wih fragments -> registers (per-warp 8 cols, all K) ----
    uint32_t wihH[8][2], wihL[8][2];
#pragma unroll
    for (int k0 = 0; k0 < 8; k0++) {
        int bk = k0 * 16 + bkoff;
        ldsm2(wihH[k0], sb + X_HI + hswz(bn, bk));
        ldsm2(wihL[k0], sb + X_LO + hswz(bn, bk));
    }
    __syncthreads();   // staging consumed; X region free

    float b4[2], awg4[2];
    b4[0] = b_ih[cA] + b_hh[cA];
    b4[1] = b_ih[cA + 1] + b_hh[cA + 1];
    awg4[0] = attn_W[cA] * ln_g[cA];
    awg4[1] = attn_W[cA + 1] * ln_g[cA + 1];
    const float S1 = ((float*)(sm + SCAL_O))[0];
    const float S2 = ((float*)(sm + SCAL_O))[1];

    // X loader: 4608 float4 chunks, 9 per thread
    auto loadX = [&](int t) {
#pragma unroll
        for (int j = 0; j < 9; j++) {
            int fi = tid + j * 512;
            int lr = fi >> 5, c4 = fi & 31;
            int gr = n0 + lr; if (gr > NN - 1) gr = NN - 1;
            float4 x = *(const float4*)(X + ((size_t)t * NN + gr) * 128 + c4 * 4);
            uint32_t h0 = packbf(x.x, x.y), h1 = packbf(x.z, x.w);
            float r0 = x.x - __uint_as_float(h0 << 16);
            float r1 = x.y - __uint_as_float(h0 & 0xffff0000u);
            float r2 = x.z - __uint_as_float(h1 << 16);
            float r3 = x.w - __uint_as_float(h1 & 0xffff0000u);
            uint32_t l0 = packbf(r0, r1), l1 = packbf(r2, r3);
            *(uint2*)(sm + X_HI + hswz(lr, c4 * 4)) = make_uint2(h0, h1);
            *(uint2*)(sm + X_LO + hswz(lr, c4 * 4)) = make_uint2(l0, l1);
        }
    };
    loadX(0);
    __syncthreads();

    float acc[9][4];
#pragma unroll
    for (int mt = 0; mt < 9; mt++)
#pragma unroll
        for (int i = 0; i < 4; i++) acc[mt][i] = 0.f;

    // ---- h0 = X[0]@Wih^T + bias (no relu) ----
#pragma unroll
    for (int k0 = 0; k0 < 8; k0++) {
        const int akb = akbase + k0 * 16;
#pragma unroll
        for (int mt = 0; mt < 9; mt++) {
            uint32_t xh[4], xl[4];
            ldsm4(xh, sb + X_HI + hswz(mt * 16 + ar, akb));
            ldsm4(xl, sb + X_LO + hswz(mt * 16 + ar, akb));
            mma_bf16(acc[mt], xh, wihH[k0]);
            mma_bf16(acc[mt], xh, wihL[k0]);
            mma_bf16(acc[mt], xl, wihH[k0]);
        }
    }
#pragma unroll
    for (int mt = 0; mt < 9; mt++)
#pragma unroll
        for (int rh = 0; rh < 2; rh++) {
            int r = mt * 16 + g + rh * 8;
            float v0 = acc[mt][rh * 2] + b4[0], v1 = acc[mt][rh * 2 + 1] + b4[1];
            uint32_t p0 = packbf(v0, v1);
            *(uint32_t*)(sm + H_HI + hswz(r, cA)) = p0;
            uint32_t l0 = packbf(v0 - __uint_as_float(p0 << 16),
                                 v1 - __uint_as_float(p0 & 0xffff0000u));
            *(uint32_t*)(sm + H_LO + hswz(r, cA)) = l0;
        }
    __syncthreads();

    float P[9][4];
#pragma unroll
    for (int mt = 0; mt < 9; mt++)
#pragma unroll
        for (int i = 0; i < 4; i++) P[mt][i] = 0.f;
    float rs_s = 0.f, rs_q = 0.f;   // unnormalized softmax sums (tid<144)

    // =================== time loop ===================
    for (int t = 0; t < TT; t++) {
#pragma unroll
        for (int mt = 0; mt < 9; mt++)
#pragma unroll
            for (int i = 0; i < 4; i++) acc[mt][i] = 0.f;

        // combined mma: acc = h@Whh^T + X[t]@Wih^T (6 split-bf16 products)
#pragma unroll
        for (int k0 = 0; k0 < 8; k0++) {
            int bk = k0 * 16 + bkoff;
            uint32_t bh0[2], bl0[2];
            ldsm2(bh0, sb + WHH_HI + hswz(bn, bk));
            ldsm2(bl0, sb + WHH_LO + hswz(bn, bk));
            const int akb = akbase + k0 * 16;
#pragma unroll
            for (int mt = 0; mt < 9; mt++) {
                uint32_t hh[4], hl[4], xh[4], xl[4];
                ldsm4(hh, sb + H_HI + hswz(mt * 16 + ar, akb));
                ldsm4(hl, sb + H_LO + hswz(mt * 16 + ar, akb));
                ldsm4(xh, sb + X_HI + hswz(mt * 16 + ar, akb));
                ldsm4(xl, sb + X_LO + hswz(mt * 16 + ar, akb));
                mma_bf16(acc[mt], hh, bh0);
                mma_bf16(acc[mt], hh, bl0);
                mma_bf16(acc[mt], hl, bh0);
                mma_bf16(acc[mt], xh, wihH[k0]);
                mma_bf16(acc[mt], xh, wihL[k0]);
                mma_bf16(acc[mt], xl, wihH[k0]);
            }
        }
        __syncthreads();   // h & x tiles free (RED/LP overlay usable)

        // h_{t+1} = relu(acc + bias); keep in acc; pack -> SMEM; partials
#pragma unroll
        for (int mt = 0; mt < 9; mt++)
#pragma unroll
            for (int rh = 0; rh < 2; rh++) {
                int r = mt * 16 + g + rh * 8;
                float v0 = fmaxf(acc[mt][rh * 2]     + b4[0], 0.f);
                float v1 = fmaxf(acc[mt][rh * 2 + 1] + b4[1], 0.f);
                acc[mt][rh * 2] = v0; acc[mt][rh * 2 + 1] = v1;
                uint32_t p0 = packbf(v0, v1);
                *(uint32_t*)(sm + H_HI + hswz(r, cA)) = p0;
                uint32_t l0 = packbf(v0 - __uint_as_float(p0 << 16),
                                     v1 - __uint_as_float(p0 & 0xffff0000u));
                *(uint32_t*)(sm + H_LO + hswz(r, cA)) = l0;

                float s1 = v0 + v1;
                float s2 = fmaf(v0, v0, v1 * v1);
                float lp = fmaf(v0, awg4[0], v1 * awg4[1]);
                s1 += __shfl_xor_sync(0xffffffffu, s1, 1);
                s1 += __shfl_xor_sync(0xffffffffu, s1, 2);
                s2 += __shfl_xor_sync(0xffffffffu, s2, 1);
                s2 += __shfl_xor_sync(0xffffffffu, s2, 2);
                lp += __shfl_xor_sync(0xffffffffu, lp, 1);
                lp += __shfl_xor_sync(0xffffffffu, lp, 2);
                if (q4 == 0) {
                    *(float2*)(sm + RED_O + (warp * 144 + r) * 8) = make_float2(s1, s2);
                    ((float*)(sm + LP_O))[warp * 144 + r] = lp;
                }
            }
        __syncthreads();

        // per-row finalize -> w = exp(l)*rstd  (max-free: logits bounded)
        if (tid < 144) {
            float s1 = 0.f, s2 = 0.f, lp = 0.f;
#pragma unroll
            for (int w = 0; w < 16; w++) {
                float2 v = *(float2*)(sm + RED_O + (w * 144 + tid) * 8);
                s1 += v.x; s2 += v.y;
                lp += ((float*)(sm + LP_O))[w * 144 + tid];
            }
            float mu = s1 * (1.0f / 128.0f);
            float var = fmaf(s2, 1.0f / 128.0f, -mu * mu);
            float rstd = rsqrtf(var + 1e-5f);
            float l = fmaf(rstd, lp - mu * S1, S2);
            float e = __expf(l);
            rs_s += e;
            float w = e * rstd;
            rs_q = fmaf(w, mu, rs_q);
            ((float*)(sm + RAB_O))[tid] = w;
        }
        __syncthreads();

        // P += w * h (acc holds h) ; refill X[t+1] (X region free, RED/LP dead)
#pragma unroll
        for (int mt = 0; mt < 9; mt++)
#pragma unroll
            for (int rh = 0; rh < 2; rh++) {
                int r = mt * 16 + g + rh * 8;
                float w = ((float*)(sm + RAB_O))[r];
                P[mt][rh * 2]     = fmaf(w, acc[mt][rh * 2],     P[mt][rh * 2]);
                P[mt][rh * 2 + 1] = fmaf(w, acc[mt][rh * 2 + 1], P[mt][rh * 2 + 1]);
            }
        if (t < TT - 1) loadX(t + 1);
        __syncthreads();   // x & h tiles ready for next mma
    }

    // ---- final: out = (Σ Wd·γ·P − q·Σ(Wd·γ))/s + Σ(Wd·β) + dense_b ----
    {
        float wdg[CC][2];
#pragma unroll
        for (int c2 = 0; c2 < CC; c2++) {
            wdg[c2][0] = dense_W[c2 * 128 + cA] * ln_g[cA];
            wdg[c2][1] = dense_W[c2 * 128 + cA + 1] * ln_g[cA + 1];
        }
        // OUTS overlay over h/x regions: [16][144][10] fp32
#pragma unroll
        for (int mt = 0; mt < 9; mt++)
#pragma unroll
            for (int rh = 0; rh < 2; rh++) {
                int r = mt * 16 + g + rh * 8;
                float pv0 = P[mt][rh * 2], pv1 = P[mt][rh * 2 + 1];
#pragma unroll
                for (int c2 = 0; c2 < CC; c2++) {
                    float s = fmaf(pv0, wdg[c2][0], pv1 * wdg[c2][1]);
                    s += __shfl_xor_sync(0xffffffffu, s, 1);
                    s += __shfl_xor_sync(0xffffffffu, s, 2);
                    if (q4 == 0)
                        ((float*)(sm + OUTS_O))[(warp * 144 + r) * CC + c2] = s;
                }
            }
    }
    __syncthreads();
    if (tid < 144 && (n0 + tid) < NN) {
        float inv = 1.0f / rs_s;
#pragma unroll
        for (int c2 = 0; c2 < CC; c2++) {
            float tot = 0.f;
#pragma unroll
            for (int w = 0; w < 16; w++)
                tot += ((float*)(sm + OUTS_O))[(w * 144 + tid) * CC + c2];
            float val = (tot - rs_q * ((float*)(sm + WGS_O))[c2]) * inv
                        + ((float*)(sm + WB_O))[c2] + dense_b[c2];
            out[(n0 + tid) * CC + c2] = val;
        }
    }
}

// ===========================================================================
extern "C" void kernel_launch(void* const* d_in, const int* in_sizes, int n_in,
                              void* d_out, int out_size)
{
    const float* X       = (const float*)d_in[0];
    const float* W_ih    = (const float*)d_in[1];
    const float* W_hh    = (const float*)d_in[2];
    const float* b_ih    = (const float*)d_in[3];
    const float* b_hh    = (const float*)d_in[4];
    const float* ln_g    = (const float*)d_in[5];
    const float* ln_b    = (const float*)d_in[6];
    const float* attn_W  = (const float*)d_in[7];
    const float* attn_b  = (const float*)d_in[8];
    const float* dense_W = (const float*)d_in[9];
    const float* dense_b = (const float*)d_in[10];
    float* out = (float*)d_out;

    cudaFuncSetAttribute(grn_one, cudaFuncAttributeMaxDynamicSharedMemorySize, SMEMSZ);

    grn_one<<<(NN + 143) / 144, 512, SMEMSZ>>>(
        X, W_ih, W_hh, b_ih, b_hh, ln_g, ln_b, attn_W, attn_b,
        dense_W, dense_b, out);
}

// round 9
// speedup vs baseline: 1.0169x; 1.0169x over previous
#include <cuda_runtime.h>
#include <cuda_bf16.h>
#include <cstdint>

#define TT 32
#define NN 20000
#define CC 10

// Scratch: U[t][n][c] = X[t,n,:]@W_ih^T + b_ih + b_hh  (fp32, 327.68 MB)
__device__ float g_U[(size_t)TT * NN * 128];

// ---------------------------------------------------------------------------
__device__ __forceinline__ uint32_t smem_u32_of(const void* p) {
    uint32_t a;
    asm("{ .reg .u64 t; cvta.to.shared.u64 t, %1; cvt.u32.u64 %0, t; }" : "=r"(a) : "l"(p));
    return a;
}
__device__ __forceinline__ void mma_bf16(float* c, const uint32_t* a, const uint32_t* b) {
    asm volatile("mma.sync.aligned.m16n8k16.row.col.f32.bf16.bf16.f32 "
        "{%0,%1,%2,%3}, {%4,%5,%6,%7}, {%8,%9}, {%0,%1,%2,%3};"
        : "+f"(c[0]), "+f"(c[1]), "+f"(c[2]), "+f"(c[3])
        : "r"(a[0]), "r"(a[1]), "r"(a[2]), "r"(a[3]), "r"(b[0]), "r"(b[1]));
}
__device__ __forceinline__ void ldsm4(uint32_t* r, uint32_t addr) {
    asm volatile("ldmatrix.sync.aligned.m8n8.x4.shared.b16 {%0,%1,%2,%3}, [%4];"
        : "=r"(r[0]), "=r"(r[1]), "=r"(r[2]), "=r"(r[3]) : "r"(addr));
}
__device__ __forceinline__ void ldsm2(uint32_t* r, uint32_t addr) {
    asm volatile("ldmatrix.sync.aligned.m8n8.x2.shared.b16 {%0,%1}, [%2];"
        : "=r"(r[0]), "=r"(r[1]) : "r"(addr));
}
// swizzled byte offset in a [rows][128] bf16 tile (256 B/row)
__device__ __forceinline__ uint32_t hswz(int r, int k) {
    int k8 = k >> 3;
    int s = (k8 & 8) | ((k8 ^ r) & 7);
    return (uint32_t)(r * 256 + s * 16 + (k & 7) * 2);
}
__device__ __forceinline__ uint32_t packbf(float a, float b) {
    uint32_t p;
    asm("cvt.rn.bf16x2.f32 %0, %1, %2;" : "=r"(p) : "f"(b), "f"(a));
    return p;
}
__device__ __forceinline__ void conv_weight(const float* __restrict__ W,
                                            char* hi, char* lo, int tid, int nthr) {
    for (int idx = tid; idx < 16384; idx += nthr) {
        int r = idx >> 7, k = idx & 127;
        float w = W[idx];
        __nv_bfloat16 wh = __float2bfloat16(w);
        uint32_t o = hswz(r, k);
        *(__nv_bfloat16*)(hi + o) = wh;
        *(__nv_bfloat16*)(lo + o) = __float2bfloat16(w - __bfloat162float(wh));
    }
}
#define CP16(dst, src) asm volatile("cp.async.cg.shared.global [%0], [%1], 16;" :: "r"(dst), "l"(src))
#define CP_COMMIT()    asm volatile("cp.async.commit_group;" ::: "memory")
#define CP_WAIT0()     asm volatile("cp.async.wait_group 0;" ::: "memory")

// ===========================================================================
// Kernel 1: U = X@Wih^T + (b_ih+b_hh). 64 rows/CTA, grid 10000, 256 thr,
// occ 2. Wih hi/lo in SMEM; 8 warps n-split (n16); split-bf16 3 products.
// ===========================================================================
#define K1_WIH_HI 0
#define K1_WIH_LO 32768
#define K1_X_HI   65536     /* 64 x 256 B */
#define K1_X_LO   81920
#define K1_STAGE  65536     /* overlay after mma: 64 x 512 B fp32 */
#define K1_SMEM   98816

__global__ __launch_bounds__(256, 2) void u_gemm(
    const float* __restrict__ X,
    const float* __restrict__ W_ih,
    const float* __restrict__ b_ih,
    const float* __restrict__ b_hh)
{
    extern __shared__ char sm[];
    const uint32_t sb = smem_u32_of(sm);
    const int tid = threadIdx.x, warp = tid >> 5, lane = tid & 31;
    const int g = lane >> 2, q4 = lane & 3;
    const int nw = warp * 16;
    const int cA = nw + q4 * 2;
    const int ar = lane & 15;
    const int akbase = ((lane >> 4) << 3);
    const int bn = nw + (lane & 7);
    const int bkoff = (((lane >> 3) & 1) << 3);
    const size_t rows0 = (size_t)blockIdx.x * 64;

    conv_weight(W_ih, sm + K1_WIH_HI, sm + K1_WIH_LO, tid, 256);

    // X tile: 64x128 fp32 -> split-bf16 swizzled
    {
        const float4* X4 = (const float4*)X;
#pragma unroll
        for (int j = 0; j < 8; j++) {
            int fi = tid + j * 256;          // 0..2047
            int r = fi >> 5, c4 = fi & 31;
            float4 x = X4[(rows0 + r) * 32 + c4];
            uint32_t h0 = packbf(x.x, x.y), h1 = packbf(x.z, x.w);
            float r0 = x.x - __uint_as_float(h0 << 16);
            float r1 = x.y - __uint_as_float(h0 & 0xffff0000u);
            float r2 = x.z - __uint_as_float(h1 << 16);
            float r3 = x.w - __uint_as_float(h1 & 0xffff0000u);
            uint32_t l0 = packbf(r0, r1), l1 = packbf(r2, r3);
            *(uint2*)(sm + K1_X_HI + hswz(r, c4 * 4)) = make_uint2(h0, h1);
            *(uint2*)(sm + K1_X_LO + hswz(r, c4 * 4)) = make_uint2(l0, l1);
        }
    }
    __syncthreads();

    float acc[4][2][4];
#pragma unroll
    for (int mt = 0; mt < 4; mt++)
#pragma unroll
        for (int nt = 0; nt < 2; nt++)
#pragma unroll
            for (int i = 0; i < 4; i++) acc[mt][nt][i] = 0.f;

#pragma unroll
    for (int k0 = 0; k0 < 8; k0++) {
        int bk = k0 * 16 + bkoff;
        uint32_t bh0[2], bh1[2], bl0[2], bl1[2];
        ldsm2(bh0, sb + K1_WIH_HI + hswz(bn, bk));
        ldsm2(bh1, sb + K1_WIH_HI + hswz(bn + 8, bk));
        ldsm2(bl0, sb + K1_WIH_LO + hswz(bn, bk));
        ldsm2(bl1, sb + K1_WIH_LO + hswz(bn + 8, bk));
        const int akb = akbase + k0 * 16;
#pragma unroll
        for (int mt = 0; mt < 4; mt++) {
            uint32_t xh[4], xl[4];
            ldsm4(xh, sb + K1_X_HI + hswz(mt * 16 + ar, akb));
            ldsm4(xl, sb + K1_X_LO + hswz(mt * 16 + ar, akb));
            mma_bf16(acc[mt][0], xh, bh0);
            mma_bf16(acc[mt][1], xh, bh1);
            mma_bf16(acc[mt][0], xh, bl0);
            mma_bf16(acc[mt][1], xh, bl1);
            mma_bf16(acc[mt][0], xl, bh0);
            mma_bf16(acc[mt][1], xl, bh1);
        }
    }
    __syncthreads();   // x tiles free -> stage overlay

    float b4[4];
    b4[0] = b_ih[cA] + b_hh[cA];         b4[1] = b_ih[cA + 1] + b_hh[cA + 1];
    b4[2] = b_ih[cA + 8] + b_hh[cA + 8]; b4[3] = b_ih[cA + 9] + b_hh[cA + 9];
#pragma unroll
    for (int mt = 0; mt < 4; mt++)
#pragma unroll
        for (int rh = 0; rh < 2; rh++) {
            int r = mt * 16 + g + rh * 8;
            *(float2*)(sm + K1_STAGE + r * 512 + cA * 4) =
                make_float2(acc[mt][0][rh * 2] + b4[0], acc[mt][0][rh * 2 + 1] + b4[1]);
            *(float2*)(sm + K1_STAGE + r * 512 + (cA + 8) * 4) =
                make_float2(acc[mt][1][rh * 2] + b4[2], acc[mt][1][rh * 2 + 1] + b4[3]);
        }
    __syncthreads();
    {
        float4* U4 = (float4*)g_U;
#pragma unroll
        for (int j = 0; j < 8; j++) {
            int fi = tid + j * 256;
            int r = fi >> 5, c4 = fi & 31;
            U4[(rows0 + r) * 32 + c4] = *(float4*)(sm + K1_STAGE + fi * 16);
        }
    }
}

// ===========================================================================
// Kernel 2: fused recurrence + LN + softmax-attention + dense head.
// 144 rows/CTA, grid 139 (one wave), 384 thr = 12 warps = wm3 x wn4 (n32).
// U[t] via cp.async (single 72KB buffer, one step ahead).
// ===========================================================================
#define WHH_HI 0
#define WHH_LO 32768
#define H_HI   65536     /* 144 x 256 B */
#define H_LO   102400
#define UBUF   139264    /* 144 x 512 B fp32; OUTS overlay at the end */
#define RED_O  212992    /* float2 [4][144] */
#define LP_O   217600    /* float  [4][144] */
#define RAB_O  219904    /* float  [144] */
#define SCAL_O 220480    /* float[2] */
#define WGS_O  220488    /* float[10] */
#define WB_O   220528    /* float[10] */
#define K2_SMEM 220576

__global__ __launch_bounds__(384, 1) void rnn_fused(
    const float* __restrict__ W_hh,
    const float* __restrict__ ln_g,  const float* __restrict__ ln_b,
    const float* __restrict__ attn_W, const float* __restrict__ attn_b,
    const float* __restrict__ dense_W, const float* __restrict__ dense_b,
    float* __restrict__ out)
{
    extern __shared__ char sm[];
    const uint32_t sb = smem_u32_of(sm);
    const int tid = threadIdx.x, warp = tid >> 5, lane = tid & 31;
    const int g = lane >> 2, q4 = lane & 3;
    const int mgrp = warp >> 2;          // 0..2, rows [48*mgrp, +48)
    const int wnid = warp & 3;           // 0..3, cols [32*wnid, +32)
    const int nw = wnid * 32;
    const int rb = mgrp * 48;
    const int ar = lane & 15;
    const int akbase = ((lane >> 4) << 3);
    const int bnl = lane & 7;
    const int bksel = (((lane >> 3) & 1) << 3);
    const int n0 = blockIdx.x * 144;

    // cp.async U tile loader (144 x 512 B = 4608 chunks, 12/thread)
    auto cpU = [&](int t) {
#pragma unroll
        for (int j = 0; j < 12; j++) {
            int fi = tid + j * 384;
            int r = fi >> 5, c4 = fi & 31;
            int gr = n0 + r; if (gr > NN - 1) gr = NN - 1;
            CP16(sb + UBUF + fi * 16, g_U + ((size_t)t * NN + gr) * 128 + c4 * 4);
        }
        CP_COMMIT();
    };
    cpU(0);

    conv_weight(W_hh, sm + WHH_HI, sm + WHH_LO, tid, 384);
    if (tid == 0) {
        float s1 = 0.f, s2 = 0.f;
        for (int c = 0; c < 128; c++) {
            s1 += attn_W[c] * ln_g[c];
            s2 += attn_W[c] * ln_b[c];
        }
        ((float*)(sm + SCAL_O))[0] = s1;
        ((float*)(sm + SCAL_O))[1] = s2 + attn_b[0];
    }
    if (tid >= 32 && tid < 32 + CC) {
        int c2 = tid - 32;
        float wg = 0.f, wb = 0.f;
        for (int k = 0; k < 128; k++) {
            float wd = dense_W[c2 * 128 + k];
            wg += wd * ln_g[k];
            wb += wd * ln_b[k];
        }
        ((float*)(sm + WGS_O))[c2] = wg;
        ((float*)(sm + WB_O))[c2] = wb;
    }

    float aw2[4][2];
#pragma unroll
    for (int nt = 0; nt < 4; nt++) {
        int c = nw + nt * 8 + q4 * 2;
        aw2[nt][0] = attn_W[c] * ln_g[c];
        aw2[nt][1] = attn_W[c + 1] * ln_g[c + 1];
    }

    CP_WAIT0();
    __syncthreads();
    const float S1 = ((float*)(sm + SCAL_O))[0];
    const float S2 = ((float*)(sm + SCAL_O))[1];

    // h0 = U[0] (biases already folded in k1; no relu): pack into h tiles
#pragma unroll
    for (int mt = 0; mt < 3; mt++)
#pragma unroll
        for (int rh = 0; rh < 2; rh++) {
            int r = rb + mt * 16 + g + rh * 8;
#pragma unroll
            for (int nt = 0; nt < 4; nt++) {
                int c = nw + nt * 8 + q4 * 2;
                float2 u = *(float2*)(sm + UBUF + r * 512 + c * 4);
                uint32_t p0 = packbf(u.x, u.y);
                *(uint32_t*)(sm + H_HI + hswz(r, c)) = p0;
                uint32_t l0 = packbf(u.x - __uint_as_float(p0 << 16),
                                     u.y - __uint_as_float(p0 & 0xffff0000u));
                *(uint32_t*)(sm + H_LO + hswz(r, c)) = l0;
            }
        }
    __syncthreads();

    float P[3][4][4];
#pragma unroll
    for (int mt = 0; mt < 3; mt++)
#pragma unroll
        for (int nt = 0; nt < 4; nt++)
#pragma unroll
            for (int i = 0; i < 4; i++) P[mt][nt][i] = 0.f;
    float rs_s = 0.f, rs_q = 0.f;
    float acc[3][4][4];

    // =================== time loop ===================
    for (int t = 0; t < TT; t++) {
#pragma unroll
        for (int mt = 0; mt < 3; mt++)
#pragma unroll
            for (int nt = 0; nt < 4; nt++)
#pragma unroll
                for (int i = 0; i < 4; i++) acc[mt][nt][i] = 0.f;

        // acc = h @ Whh^T (3 split-bf16 products, n32 per warp)
#pragma unroll
        for (int k0 = 0; k0 < 8; k0++) {
            int bk = k0 * 16 + bksel;
            uint32_t bh[4][2], bl[4][2];
#pragma unroll
            for (int nt = 0; nt < 4; nt++) {
                ldsm2(bh[nt], sb + WHH_HI + hswz(nw + nt * 8 + bnl, bk));
                ldsm2(bl[nt], sb + WHH_LO + hswz(nw + nt * 8 + bnl, bk));
            }
            const int akb = akbase + k0 * 16;
#pragma unroll
            for (int mt = 0; mt < 3; mt++) {
                uint32_t hh[4], hl[4];
                ldsm4(hh, sb + H_HI + hswz(rb + mt * 16 + ar, akb));
                ldsm4(hl, sb + H_LO + hswz(rb + mt * 16 + ar, akb));
#pragma unroll
                for (int nt = 0; nt < 4; nt++) {
                    mma_bf16(acc[mt][nt], hh, bh[nt]);
                    mma_bf16(acc[mt][nt], hh, bl[nt]);
                    mma_bf16(acc[mt][nt], hl, bh[nt]);
                }
            }
        }
        CP_WAIT0();        // U[t] landed
        __syncthreads();   // all mma reads of h done; U visible

        // h_{t+1} = relu(acc + U); pack; LN/logit partials
#pragma unroll
        for (int mt = 0; mt < 3; mt++)
#pragma unroll
            for (int rh = 0; rh < 2; rh++) {
                int r = rb + mt * 16 + g + rh * 8;
                float s1 = 0.f, s2 = 0.f, lp = 0.f;
#pragma unroll
                for (int nt = 0; nt < 4; nt++) {
                    int c = nw + nt * 8 + q4 * 2;
                    float2 u = *(float2*)(sm + UBUF + r * 512 + c * 4);
                    float v0 = fmaxf(acc[mt][nt][rh * 2]     + u.x, 0.f);
                    float v1 = fmaxf(acc[mt][nt][rh * 2 + 1] + u.y, 0.f);
                    acc[mt][nt][rh * 2] = v0; acc[mt][nt][rh * 2 + 1] = v1;
                    uint32_t p0 = packbf(v0, v1);
                    *(uint32_t*)(sm + H_HI + hswz(r, c)) = p0;
                    uint32_t l0 = packbf(v0 - __uint_as_float(p0 << 16),
                                         v1 - __uint_as_float(p0 & 0xffff0000u));
                    *(uint32_t*)(sm + H_LO + hswz(r, c)) = l0;
                    s1 += v0 + v1;
                    s2 = fmaf(v0, v0, fmaf(v1, v1, s2));
                    lp = fmaf(v0, aw2[nt][0], fmaf(v1, aw2[nt][1], lp));
                }
                s1 += __shfl_xor_sync(0xffffffffu, s1, 1);
                s1 += __shfl_xor_sync(0xffffffffu, s1, 2);
                s2 += __shfl_xor_sync(0xffffffffu, s2, 1);
                s2 += __shfl_xor_sync(0xffffffffu, s2, 2);
                lp += __shfl_xor_sync(0xffffffffu, lp, 1);
                lp += __shfl_xor_sync(0xffffffffu, lp, 2);
                if (q4 == 0) {
                    *(float2*)(sm + RED_O + (wnid * 144 + r) * 8) = make_float2(s1, s2);
                    ((float*)(sm + LP_O))[wnid * 144 + r] = lp;
                }
            }
        __syncthreads();

        // per-row finalize -> w = exp(l)*rstd (max-free; logits bounded)
        if (tid < 144) {
            float s1 = 0.f, s2 = 0.f, lp = 0.f;
#pragma unroll
            for (int w = 0; w < 4; w++) {
                float2 v = *(float2*)(sm + RED_O + (w * 144 + tid) * 8);
                s1 += v.x; s2 += v.y;
                lp += ((float*)(sm + LP_O))[w * 144 + tid];
            }
            float mu = s1 * (1.0f / 128.0f);
            float var = fmaf(s2, 1.0f / 128.0f, -mu * mu);
            float rstd = rsqrtf(var + 1e-5f);
            float l = fmaf(rstd, lp - mu * S1, S2);
            float e = __expf(l);
            rs_s += e;
            float w = e * rstd;
            rs_q = fmaf(w, mu, rs_q);
            ((float*)(sm + RAB_O))[tid] = w;
        }
        __syncthreads();

        // P += w * h (acc holds h) ; prefetch U[t+1]
#pragma unroll
        for (int mt = 0; mt < 3; mt++)
#pragma unroll
            for (int rh = 0; rh < 2; rh++) {
                int r = rb + mt * 16 + g + rh * 8;
                float w = ((float*)(sm + RAB_O))[r];
#pragma unroll
                for (int nt = 0; nt < 4; nt++) {
                    P[mt][nt][rh * 2]     = fmaf(w, acc[mt][nt][rh * 2],     P[mt][nt][rh * 2]);
                    P[mt][nt][rh * 2 + 1] = fmaf(w, acc[mt][nt][rh * 2 + 1], P[mt][nt][rh * 2 + 1]);
                }
            }
        if (t < TT - 1) cpU(t + 1);
        // no end sync needed: next mma reads h (synced), cp.async fills UBUF
        // (not read until next CP_WAIT0), RAB rewritten only after next sync.
    }

    // ---- final: out = (Σ Wd·γ·P − q·Σ(Wd·γ))/s + Σ(Wd·β) + dense_b ----
    {
        float gl[4][2];
#pragma unroll
        for (int nt = 0; nt < 4; nt++) {
            int c = nw + nt * 8 + q4 * 2;
            gl[nt][0] = ln_g[c];
            gl[nt][1] = ln_g[c + 1];
        }
        // OUTS overlay in UBUF: [4][144][10] fp32
#pragma unroll
        for (int mt = 0; mt < 3; mt++)
#pragma unroll
            for (int rh = 0; rh < 2; rh++) {
                int r = rb + mt * 16 + g + rh * 8;
#pragma unroll
                for (int c2 = 0; c2 < CC; c2++) {
                    float s = 0.f;
#pragma unroll
                    for (int nt = 0; nt < 4; nt++) {
                        int c = nw + nt * 8 + q4 * 2;
                        s = fmaf(P[mt][nt][rh * 2],     dense_W[c2 * 128 + c] * gl[nt][0], s);
                        s = fmaf(P[mt][nt][rh * 2 + 1], dense_W[c2 * 128 + c + 1] * gl[nt][1], s);
                    }
                    s += __shfl_xor_sync(0xffffffffu, s, 1);
                    s += __shfl_xor_sync(0xffffffffu, s, 2);
                    if (q4 == 0)
                        ((float*)(sm + UBUF))[(wnid * 144 + r) * CC + c2] = s;
                }
            }
    }
    __syncthreads();
    if (tid < 144 && (n0 + tid) < NN) {
        float inv = 1.0f / rs_s;
#pragma unroll
        for (int c2 = 0; c2 < CC; c2++) {
            float tot = 0.f;
#pragma unroll
            for (int w = 0; w < 4; w++)
                tot += ((float*)(sm + UBUF))[(w * 144 + tid) * CC + c2];
            float val = (tot - rs_q * ((float*)(sm + WGS_O))[c2]) * inv
                        + ((float*)(sm + WB_O))[c2] + dense_b[c2];
            out[(n0 + tid) * CC + c2] = val;
        }
    }
}

// ===========================================================================
extern "C" void kernel_launch(void* const* d_in, const int* in_sizes, int n_in,
                              void* d_out, int out_size)
{
    const float* X       = (const float*)d_in[0];
    const float* W_ih    = (const float*)d_in[1];
    const float* W_hh    = (const float*)d_in[2];
    const float* b_ih    = (const float*)d_in[3];
    const float* b_hh    = (const float*)d_in[4];
    const float* ln_g    = (const float*)d_in[5];
    const float* ln_b    = (const float*)d_in[6];
    const float* attn_W  = (const float*)d_in[7];
    const float* attn_b  = (const float*)d_in[8];
    const float* dense_W = (const float*)d_in[9];
    const float* dense_b = (const float*)d_in[10];
    float* out = (float*)d_out;

    cudaFuncSetAttribute(u_gemm, cudaFuncAttributeMaxDynamicSharedMemorySize, K1_SMEM);
    cudaFuncSetAttribute(rnn_fused, cudaFuncAttributeMaxDynamicSharedMemorySize, K2_SMEM);

    u_gemm<<<(TT * NN) / 64, 256, K1_SMEM>>>(X, W_ih, b_ih, b_hh);
    rnn_fused<<<(NN + 143) / 144, 384, K2_SMEM>>>(W_hh, ln_g, ln_b, attn_W, attn_b,
                                                  dense_W, dense_b, out);
}

// round 10
// speedup vs baseline: 1.2795x; 1.2582x over previous
#include <cuda_runtime.h>
#include <cuda_bf16.h>
#include <cstdint>

#define TT 32
#define NN 20000
#define CC 10

// Scratch: U[t][n][c] = X[t,n,:]@W_ih^T + b_ih + b_hh  (fp32, 327.68 MB)
__device__ float g_U[(size_t)TT * NN * 128];
// Pre-converted W_ih split-bf16 tiles in SMEM-ready swizzled layout (32 KB each)
__device__ __align__(16) char g_WihH[32768];
__device__ __align__(16) char g_WihL[32768];

// ---------------------------------------------------------------------------
__device__ __forceinline__ uint32_t smem_u32_of(const void* p) {
    uint32_t a;
    asm("{ .reg .u64 t; cvta.to.shared.u64 t, %1; cvt.u32.u64 %0, t; }" : "=r"(a) : "l"(p));
    return a;
}
__device__ __forceinline__ void mma_bf16(float* c, const uint32_t* a, const uint32_t* b) {
    asm volatile("mma.sync.aligned.m16n8k16.row.col.f32.bf16.bf16.f32 "
        "{%0,%1,%2,%3}, {%4,%5,%6,%7}, {%8,%9}, {%0,%1,%2,%3};"
        : "+f"(c[0]), "+f"(c[1]), "+f"(c[2]), "+f"(c[3])
        : "r"(a[0]), "r"(a[1]), "r"(a[2]), "r"(a[3]), "r"(b[0]), "r"(b[1]));
}
__device__ __forceinline__ void ldsm4(uint32_t* r, uint32_t addr) {
    asm volatile("ldmatrix.sync.aligned.m8n8.x4.shared.b16 {%0,%1,%2,%3}, [%4];"
        : "=r"(r[0]), "=r"(r[1]), "=r"(r[2]), "=r"(r[3]) : "r"(addr));
}
__device__ __forceinline__ void ldsm2(uint32_t* r, uint32_t addr) {
    asm volatile("ldmatrix.sync.aligned.m8n8.x2.shared.b16 {%0,%1}, [%2];"
        : "=r"(r[0]), "=r"(r[1]) : "r"(addr));
}
// swizzled byte offset in a [rows][128] bf16 tile (256 B/row)
__device__ __forceinline__ uint32_t hswz(int r, int k) {
    int k8 = k >> 3;
    int s = (k8 & 8) | ((k8 ^ r) & 7);
    return (uint32_t)(r * 256 + s * 16 + (k & 7) * 2);
}
__device__ __forceinline__ uint32_t packbf(float a, float b) {
    uint32_t p;
    asm("cvt.rn.bf16x2.f32 %0, %1, %2;" : "=r"(p) : "f"(b), "f"(a));
    return p;
}
__device__ __forceinline__ void conv_weight(const float* __restrict__ W,
                                            char* hi, char* lo, int tid, int nthr) {
    for (int idx = tid; idx < 16384; idx += nthr) {
        int r = idx >> 7, k = idx & 127;
        float w = W[idx];
        __nv_bfloat16 wh = __float2bfloat16(w);
        uint32_t o = hswz(r, k);
        *(__nv_bfloat16*)(hi + o) = wh;
        *(__nv_bfloat16*)(lo + o) = __float2bfloat16(w - __bfloat162float(wh));
    }
}
#define CP16(dst, src) asm volatile("cp.async.cg.shared.global [%0], [%1], 16;" :: "r"(dst), "l"(src))
#define CP_COMMIT()    asm volatile("cp.async.commit_group;" ::: "memory")
#define CP_WAIT0()     asm volatile("cp.async.wait_group 0;" ::: "memory")

// ===========================================================================
// Kernel 0: one-time W_ih -> split-bf16 swizzled global tiles.
// ===========================================================================
__global__ void conv_wih_kernel(const float* __restrict__ W_ih) {
    conv_weight(W_ih, g_WihH, g_WihL, threadIdx.x, 256);
}

// ===========================================================================
// Kernel 1: U = X@Wih^T + (b_ih+b_hh). 64 rows/CTA, grid 10000, 256 thr,
// occ 2. Prepared W tiles pulled via cp.async (no per-CTA conversion).
// ===========================================================================
#define K1_WIH_HI 0
#define K1_WIH_LO 32768
#define K1_X_HI   65536     /* 64 x 256 B */
#define K1_X_LO   81920
#define K1_STAGE  65536     /* overlay after mma: 64 x 512 B fp32 */
#define K1_SMEM   98304

__global__ __launch_bounds__(256, 2) void u_gemm(
    const float* __restrict__ X,
    const float* __restrict__ b_ih,
    const float* __restrict__ b_hh)
{
    extern __shared__ char sm[];
    const uint32_t sb = smem_u32_of(sm);
    const int tid = threadIdx.x, warp = tid >> 5, lane = tid & 31;
    const int g = lane >> 2, q4 = lane & 3;
    const int nw = warp * 16;
    const int cA = nw + q4 * 2;
    const int ar = lane & 15;
    const int akbase = ((lane >> 4) << 3);
    const int bn = nw + (lane & 7);
    const int bkoff = (((lane >> 3) & 1) << 3);
    const size_t rows0 = (size_t)blockIdx.x * 64;

    // W tiles via cp.async (4096 16B chunks: 16/thread)
#pragma unroll
    for (int j = 0; j < 8; j++) {
        int fi = tid + j * 256;                   // 0..2047
        CP16(sb + K1_WIH_HI + fi * 16, g_WihH + fi * 16);
        CP16(sb + K1_WIH_LO + fi * 16, g_WihL + fi * 16);
    }
    CP_COMMIT();

    // X tile: 64x128 fp32 -> split-bf16 swizzled (overlaps W cp.async)
    {
        const float4* X4 = (const float4*)X;
#pragma unroll
        for (int j = 0; j < 8; j++) {
            int fi = tid + j * 256;               // 0..2047
            int r = fi >> 5, c4 = fi & 31;
            float4 x = X4[(rows0 + r) * 32 + c4];
            uint32_t h0 = packbf(x.x, x.y), h1 = packbf(x.z, x.w);
            float r0 = x.x - __uint_as_float(h0 << 16);
            float r1 = x.y - __uint_as_float(h0 & 0xffff0000u);
            float r2 = x.z - __uint_as_float(h1 << 16);
            float r3 = x.w - __uint_as_float(h1 & 0xffff0000u);
            uint32_t l0 = packbf(r0, r1), l1 = packbf(r2, r3);
            *(uint2*)(sm + K1_X_HI + hswz(r, c4 * 4)) = make_uint2(h0, h1);
            *(uint2*)(sm + K1_X_LO + hswz(r, c4 * 4)) = make_uint2(l0, l1);
        }
    }
    CP_WAIT0();
    __syncthreads();

    float acc[4][2][4];
#pragma unroll
    for (int mt = 0; mt < 4; mt++)
#pragma unroll
        for (int nt = 0; nt < 2; nt++)
#pragma unroll
            for (int i = 0; i < 4; i++) acc[mt][nt][i] = 0.f;

#pragma unroll
    for (int k0 = 0; k0 < 8; k0++) {
        int bk = k0 * 16 + bkoff;
        uint32_t bh0[2], bh1[2], bl0[2], bl1[2];
        ldsm2(bh0, sb + K1_WIH_HI + hswz(bn, bk));
        ldsm2(bh1, sb + K1_WIH_HI + hswz(bn + 8, bk));
        ldsm2(bl0, sb + K1_WIH_LO + hswz(bn, bk));
        ldsm2(bl1, sb + K1_WIH_LO + hswz(bn + 8, bk));
        const int akb = akbase + k0 * 16;
#pragma unroll
        for (int mt = 0; mt < 4; mt++) {
            uint32_t xh[4], xl[4];
            ldsm4(xh, sb + K1_X_HI + hswz(mt * 16 + ar, akb));
            ldsm4(xl, sb + K1_X_LO + hswz(mt * 16 + ar, akb));
            mma_bf16(acc[mt][0], xh, bh0);
            mma_bf16(acc[mt][1], xh, bh1);
            mma_bf16(acc[mt][0], xh, bl0);
            mma_bf16(acc[mt][1], xh, bl1);
            mma_bf16(acc[mt][0], xl, bh0);
            mma_bf16(acc[mt][1], xl, bh1);
        }
    }
    __syncthreads();   // x tiles free -> stage overlay

    float b4[4];
    b4[0] = b_ih[cA] + b_hh[cA];         b4[1] = b_ih[cA + 1] + b_hh[cA + 1];
    b4[2] = b_ih[cA + 8] + b_hh[cA + 8]; b4[3] = b_ih[cA + 9] + b_hh[cA + 9];
#pragma unroll
    for (int mt = 0; mt < 4; mt++)
#pragma unroll
        for (int rh = 0; rh < 2; rh++) {
            int r = mt * 16 + g + rh * 8;
            *(float2*)(sm + K1_STAGE + r * 512 + cA * 4) =
                make_float2(acc[mt][0][rh * 2] + b4[0], acc[mt][0][rh * 2 + 1] + b4[1]);
            *(float2*)(sm + K1_STAGE + r * 512 + (cA + 8) * 4) =
                make_float2(acc[mt][1][rh * 2] + b4[2], acc[mt][1][rh * 2 + 1] + b4[3]);
        }
    __syncthreads();
    {
        float4* U4 = (float4*)g_U;
#pragma unroll
        for (int j = 0; j < 8; j++) {
            int fi = tid + j * 256;
            int r = fi >> 5, c4 = fi & 31;
            U4[(rows0 + r) * 32 + c4] = *(float4*)(sm + K1_STAGE + fi * 16);
        }
    }
}

// ===========================================================================
// Kernel 2: fused recurrence + LN + softmax-attention + dense head.
// 144 rows/CTA, grid 139 (one wave), 384 thr = 12 warps = wm3 x wn4 (n32).
// (unchanged from the measured 252 us version)
// ===========================================================================
#define WHH_HI 0
#define WHH_LO 32768
#define H_HI   65536     /* 144 x 256 B */
#define H_LO   102400
#define UBUF   139264    /* 144 x 512 B fp32; OUTS overlay at the end */
#define RED_O  212992    /* float2 [4][144] */
#define LP_O   217600    /* float  [4][144] */
#define RAB_O  219904    /* float  [144] */
#define SCAL_O 220480    /* float[2] */
#define WGS_O  220488    /* float[10] */
#define WB_O   220528    /* float[10] */
#define K2_SMEM 220576

__global__ __launch_bounds__(384, 1) void rnn_fused(
    const float* __restrict__ W_hh,
    const float* __restrict__ ln_g,  const float* __restrict__ ln_b,
    const float* __restrict__ attn_W, const float* __restrict__ attn_b,
    const float* __restrict__ dense_W, const float* __restrict__ dense_b,
    float* __restrict__ out)
{
    extern __shared__ char sm[];
    const uint32_t sb = smem_u32_of(sm);
    const int tid = threadIdx.x, warp = tid >> 5, lane = tid & 31;
    const int g = lane >> 2, q4 = lane & 3;
    const int mgrp = warp >> 2;          // 0..2, rows [48*mgrp, +48)
    const int wnid = warp & 3;           // 0..3, cols [32*wnid, +32)
    const int nw = wnid * 32;
    const int rb = mgrp * 48;
    const int ar = lane & 15;
    const int akbase = ((lane >> 4) << 3);
    const int bnl = lane & 7;
    const int bksel = (((lane >> 3) & 1) << 3);
    const int n0 = blockIdx.x * 144;

    auto cpU = [&](int t) {
#pragma unroll
        for (int j = 0; j < 12; j++) {
            int fi = tid + j * 384;
            int r = fi >> 5, c4 = fi & 31;
            int gr = n0 + r; if (gr > NN - 1) gr = NN - 1;
            CP16(sb + UBUF + fi * 16, g_U + ((size_t)t * NN + gr) * 128 + c4 * 4);
        }
        CP_COMMIT();
    };
    cpU(0);

    conv_weight(W_hh, sm + WHH_HI, sm + WHH_LO, tid, 384);
    if (tid == 0) {
        float s1 = 0.f, s2 = 0.f;
        for (int c = 0; c < 128; c++) {
            s1 += attn_W[c] * ln_g[c];
            s2 += attn_W[c] * ln_b[c];
        }
        ((float*)(sm + SCAL_O))[0] = s1;
        ((float*)(sm + SCAL_O))[1] = s2 + attn_b[0];
    }
    if (tid >= 32 && tid < 32 + CC) {
        int c2 = tid - 32;
        float wg = 0.f, wb = 0.f;
        for (int k = 0; k < 128; k++) {
            float wd = dense_W[c2 * 128 + k];
            wg += wd * ln_g[k];
            wb += wd * ln_b[k];
        }
        ((float*)(sm + WGS_O))[c2] = wg;
        ((float*)(sm + WB_O))[c2] = wb;
    }

    float aw2[4][2];
#pragma unroll
    for (int nt = 0; nt < 4; nt++) {
        int c = nw + nt * 8 + q4 * 2;
        aw2[nt][0] = attn_W[c] * ln_g[c];
        aw2[nt][1] = attn_W[c + 1] * ln_g[c + 1];
    }

    CP_WAIT0();
    __syncthreads();
    const float S1 = ((float*)(sm + SCAL_O))[0];
    const float S2 = ((float*)(sm + SCAL_O))[1];

    // h0 = U[0] (biases folded in k1; no relu): pack into h tiles
#pragma unroll
    for (int mt = 0; mt < 3; mt++)
#pragma unroll
        for (int rh = 0; rh < 2; rh++) {
            int r = rb + mt * 16 + g + rh * 8;
#pragma unroll
            for (int nt = 0; nt < 4; nt++) {
                int c = nw + nt * 8 + q4 * 2;
                float2 u = *(float2*)(sm + UBUF + r * 512 + c * 4);
                uint32_t p0 = packbf(u.x, u.y);
                *(uint32_t*)(sm + H_HI + hswz(r, c)) = p0;
                uint32_t l0 = packbf(u.x - __uint_as_float(p0 << 16),
                                     u.y - __uint_as_float(p0 & 0xffff0000u));
                *(uint32_t*)(sm + H_LO + hswz(r, c)) = l0;
            }
        }
    __syncthreads();

    float P[3][4][4];
#pragma unroll
    for (int mt = 0; mt < 3; mt++)
#pragma unroll
        for (int nt = 0; nt < 4; nt++)
#pragma unroll
            for (int i = 0; i < 4; i++) P[mt][nt][i] = 0.f;
    float rs_s = 0.f, rs_q = 0.f;
    float acc[3][4][4];

    for (int t = 0; t < TT; t++) {
#pragma unroll
        for (int mt = 0; mt < 3; mt++)
#pragma unroll
            for (int nt = 0; nt < 4; nt++)
#pragma unroll
                for (int i = 0; i < 4; i++) acc[mt][nt][i] = 0.f;

        // acc = h @ Whh^T (3 split-bf16 products, n32 per warp)
#pragma unroll
        for (int k0 = 0; k0 < 8; k0++) {
            int bk = k0 * 16 + bksel;
            uint32_t bh[4][2], bl[4][2];
#pragma unroll
            for (int nt = 0; nt < 4; nt++) {
                ldsm2(bh[nt], sb + WHH_HI + hswz(nw + nt * 8 + bnl, bk));
                ldsm2(bl[nt], sb + WHH_LO + hswz(nw + nt * 8 + bnl, bk));
            }
            const int akb = akbase + k0 * 16;
#pragma unroll
            for (int mt = 0; mt < 3; mt++) {
                uint32_t hh[4], hl[4];
                ldsm4(hh, sb + H_HI + hswz(rb + mt * 16 + ar, akb));
                ldsm4(hl, sb + H_LO + hswz(rb + mt * 16 + ar, akb));
#pragma unroll
                for (int nt = 0; nt < 4; nt++) {
                    mma_bf16(acc[mt][nt], hh, bh[nt]);
                    mma_bf16(acc[mt][nt], hh, bl[nt]);
                    mma_bf16(acc[mt][nt], hl, bh[nt]);
                }
            }
        }
        CP_WAIT0();
        __syncthreads();

        // h_{t+1} = relu(acc + U); pack; LN/logit partials
#pragma unroll
        for (int mt = 0; mt < 3; mt++)
#pragma unroll
            for (int rh = 0; rh < 2; rh++) {
                int r = rb + mt * 16 + g + rh * 8;
                float s1 = 0.f, s2 = 0.f, lp = 0.f;
#pragma unroll
                for (int nt = 0; nt < 4; nt++) {
                    int c = nw + nt * 8 + q4 * 2;
                    float2 u = *(float2*)(sm + UBUF + r * 512 + c * 4);
                    float v0 = fmaxf(acc[mt][nt][rh * 2]     + u.x, 0.f);
                    float v1 = fmaxf(acc[mt][nt][rh * 2 + 1] + u.y, 0.f);
                    acc[mt][nt][rh * 2] = v0; acc[mt][nt][rh * 2 + 1] = v1;
                    uint32_t p0 = packbf(v0, v1);
                    *(uint32_t*)(sm + H_HI + hswz(r, c)) = p0;
                    uint32_t l0 = packbf(v0 - __uint_as_float(p0 << 16),
                                         v1 - __uint_as_float(p0 & 0xffff0000u));
                    *(uint32_t*)(sm + H_LO + hswz(r, c)) = l0;
                    s1 += v0 + v1;
                    s2 = fmaf(v0, v0, fmaf(v1, v1, s2));
                    lp = fmaf(v0, aw2[nt][0], fmaf(v1, aw2[nt][1], lp));
                }
                s1 += __shfl_xor_sync(0xffffffffu, s1, 1);
                s1 += __shfl_xor_sync(0xffffffffu, s1, 2);
                s2 += __shfl_xor_sync(0xffffffffu, s2, 1);
                s2 += __shfl_xor_sync(0xffffffffu, s2, 2);
                lp += __shfl_xor_sync(0xffffffffu, lp, 1);
                lp += __shfl_xor_sync(0xffffffffu, lp, 2);
                if (q4 == 0) {
                    *(float2*)(sm + RED_O + (wnid * 144 + r) * 8) = make_float2(s1, s2);
                    ((float*)(sm + LP_O))[wnid * 144 + r] = lp;
                }
            }
        __syncthreads();

        // per-row finalize -> w = exp(l)*rstd (max-free; logits bounded)
        if (tid < 144) {
            float s1 = 0.f, s2 = 0.f, lp = 0.f;
#pragma unroll
            for (int w = 0; w < 4; w++) {
                float2 v = *(float2*)(sm + RED_O + (w * 144 + tid) * 8);
                s1 += v.x; s2 += v.y;
                lp += ((float*)(sm + LP_O))[w * 144 + tid];
            }
            float mu = s1 * (1.0f / 128.0f);
            float var = fmaf(s2, 1.0f / 128.0f, -mu * mu);
            float rstd = rsqrtf(var + 1e-5f);
            float l = fmaf(rstd, lp - mu * S1, S2);
            float e = __expf(l);
            rs_s += e;
            float w = e * rstd;
            rs_q = fmaf(w, mu, rs_q);
            ((float*)(sm + RAB_O))[tid] = w;
        }
        __syncthreads();

        // P += w * h (acc holds h) ; prefetch U[t+1]
#pragma unroll
        for (int mt = 0; mt < 3; mt++)
#pragma unroll
            for (int rh = 0; rh < 2; rh++) {
                int r = rb + mt * 16 + g + rh * 8;
                float w = ((float*)(sm + RAB_O))[r];
#pragma unroll
                for (int nt = 0; nt < 4; nt++) {
                    P[mt][nt][rh * 2]     = fmaf(w, acc[mt][nt][rh * 2],     P[mt][nt][rh * 2]);
                    P[mt][nt][rh * 2 + 1] = fmaf(w, acc[mt][nt][rh * 2 + 1], P[mt][nt][rh * 2 + 1]);
                }
            }
        if (t < TT - 1) cpU(t + 1);
    }

    // ---- final: out = (Σ Wd·γ·P − q·Σ(Wd·γ))/s + Σ(Wd·β) + dense_b ----
    {
        float gl[4][2];
#pragma unroll
        for (int nt = 0; nt < 4; nt++) {
            int c = nw + nt * 8 + q4 * 2;
            gl[nt][0] = ln_g[c];
            gl[nt][1] = ln_g[c + 1];
        }
#pragma unroll
        for (int mt = 0; mt < 3; mt++)
#pragma unroll
            for (int rh = 0; rh < 2; rh++) {
                int r = rb + mt * 16 + g + rh * 8;
#pragma unroll
                for (int c2 = 0; c2 < CC; c2++) {
                    float s = 0.f;
#pragma unroll
                    for (int nt = 0; nt < 4; nt++) {
                        int c = nw + nt * 8 + q4 * 2;
                        s = fmaf(P[mt][nt][rh * 2],     dense_W[c2 * 128 + c] * gl[nt][0], s);
                        s = fmaf(P[mt][nt][rh * 2 + 1], dense_W[c2 * 128 + c + 1] * gl[nt][1], s);
                    }
                    s += __shfl_xor_sync(0xffffffffu, s, 1);
                    s += __shfl_xor_sync(0xffffffffu, s, 2);
                    if (q4 == 0)
                        ((float*)(sm + UBUF))[(wnid * 144 + r) * CC + c2] = s;
                }
            }
    }
    __syncthreads();
    if (tid < 144 && (n0 + tid) < NN) {
        float inv = 1.0f / rs_s;
#pragma unroll
        for (int c2 = 0; c2 < CC; c2++) {
            float tot = 0.f;
#pragma unroll
            for (int w = 0; w < 4; w++)
                tot += ((float*)(sm + UBUF))[(w * 144 + tid) * CC + c2];
            float val = (tot - rs_q * ((float*)(sm + WGS_O))[c2]) * inv
                        + ((float*)(sm + WB_O))[c2] + dense_b[c2];
            out[(n0 + tid) * CC + c2] = val;
        }
    }
}

// ===========================================================================
extern "C" void kernel_launch(void* const* d_in, const int* in_sizes, int n_in,
                              void* d_out, int out_size)
{
    const float* X       = (const float*)d_in[0];
    const float* W_ih    = (const float*)d_in[1];
    const float* W_hh    = (const float*)d_in[2];
    const float* b_ih    = (const float*)d_in[3];
    const float* b_hh    = (const float*)d_in[4];
    const float* ln_g    = (const float*)d_in[5];
    const float* ln_b    = (const float*)d_in[6];
    const float* attn_W  = (const float*)d_in[7];
    const float* attn_b  = (const float*)d_in[8];
    const float* dense_W = (const float*)d_in[9];
    const float* dense_b = (const float*)d_in[10];
    float* out = (float*)d_out;

    cudaFuncSetAttribute(u_gemm, cudaFuncAttributeMaxDynamicSharedMemorySize, K1_SMEM);
    cudaFuncSetAttribute(rnn_fused, cudaFuncAttributeMaxDynamicSharedMemorySize, K2_SMEM);

    conv_wih_kernel<<<1, 256>>>(W_ih);
    u_gemm<<<(TT * NN) / 64, 256, K1_SMEM>>>(X, b_ih, b_hh);
    rnn_fused<<<(NN + 143) / 144, 384, K2_SMEM>>>(W_hh, ln_g, ln_b, attn_W, attn_b,
                                                  dense_W, dense_b, out);
}

// round 11
// speedup vs baseline: 1.2798x; 1.0003x over previous
#include <cuda_runtime.h>
#include <cuda_bf16.h>
#include <cstdint>

#define TT 32
#define NN 20000
#define CC 10

// Scratch: U[t][n][c] = X[t,n,:]@W_ih^T + b_ih + b_hh  (fp32, 327.68 MB)
__device__ float g_U[(size_t)TT * NN * 128];

// ---------------------------------------------------------------------------
__device__ __forceinline__ uint32_t smem_u32_of(const void* p) {
    uint32_t a;
    asm("{ .reg .u64 t; cvta.to.shared.u64 t, %1; cvt.u32.u64 %0, t; }" : "=r"(a) : "l"(p));
    return a;
}
__device__ __forceinline__ void mma_bf16(float* c, const uint32_t* a, const uint32_t* b) {
    asm volatile("mma.sync.aligned.m16n8k16.row.col.f32.bf16.bf16.f32 "
        "{%0,%1,%2,%3}, {%4,%5,%6,%7}, {%8,%9}, {%0,%1,%2,%3};"
        : "+f"(c[0]), "+f"(c[1]), "+f"(c[2]), "+f"(c[3])
        : "r"(a[0]), "r"(a[1]), "r"(a[2]), "r"(a[3]), "r"(b[0]), "r"(b[1]));
}
__device__ __forceinline__ void ldsm4(uint32_t* r, uint32_t addr) {
    asm volatile("ldmatrix.sync.aligned.m8n8.x4.shared.b16 {%0,%1,%2,%3}, [%4];"
        : "=r"(r[0]), "=r"(r[1]), "=r"(r[2]), "=r"(r[3]) : "r"(addr));
}
__device__ __forceinline__ void ldsm2(uint32_t* r, uint32_t addr) {
    asm volatile("ldmatrix.sync.aligned.m8n8.x2.shared.b16 {%0,%1}, [%2];"
        : "=r"(r[0]), "=r"(r[1]) : "r"(addr));
}
// swizzled byte offset in a [rows][128] bf16 tile (256 B/row)
__device__ __forceinline__ uint32_t hswz(int r, int k) {
    int k8 = k >> 3;
    int s = (k8 & 8) | ((k8 ^ r) & 7);
    return (uint32_t)(r * 256 + s * 16 + (k & 7) * 2);
}
__device__ __forceinline__ uint32_t packbf(float a, float b) {
    uint32_t p;
    asm("cvt.rn.bf16x2.f32 %0, %1, %2;" : "=r"(p) : "f"(b), "f"(a));
    return p;
}
__device__ __forceinline__ void conv_weight(const float* __restrict__ W,
                                            char* hi, char* lo, int tid, int nthr) {
    for (int idx = tid; idx < 16384; idx += nthr) {
        int r = idx >> 7, k = idx & 127;
        float w = W[idx];
        __nv_bfloat16 wh = __float2bfloat16(w);
        uint32_t o = hswz(r, k);
        *(__nv_bfloat16*)(hi + o) = wh;
        *(__nv_bfloat16*)(lo + o) = __float2bfloat16(w - __bfloat162float(wh));
    }
}
#define CP16(dst, src) asm volatile("cp.async.cg.shared.global [%0], [%1], 16;" :: "r"(dst), "l"(src))
#define CP_COMMIT()    asm volatile("cp.async.commit_group;" ::: "memory")
#define CP_WAIT0()     asm volatile("cp.async.wait_group 0;" ::: "memory")

// ===========================================================================
// Kernel 1 (persistent): U = X@Wih^T + (b_ih+b_hh).
// Grid 296 (occ 2), each CTA converts Wih once, loops over 64-row tiles.
// ===========================================================================
#define K1_WIH_HI 0
#define K1_WIH_LO 32768
#define K1_X_HI   65536     /* 64 x 256 B */
#define K1_X_LO   81920
#define K1_STAGE  65536     /* overlay after mma: 64 x 512 B fp32 */
#define K1_SMEM   98304
#define K1_TILES  ((TT * NN) / 64)   /* 10000 */

__global__ __launch_bounds__(256, 2) void u_gemm(
    const float* __restrict__ X,
    const float* __restrict__ W_ih,
    const float* __restrict__ b_ih,
    const float* __restrict__ b_hh)
{
    extern __shared__ char sm[];
    const uint32_t sb = smem_u32_of(sm);
    const int tid = threadIdx.x, warp = tid >> 5, lane = tid & 31;
    const int g = lane >> 2, q4 = lane & 3;
    const int nw = warp * 16;
    const int cA = nw + q4 * 2;
    const int ar = lane & 15;
    const int akbase = ((lane >> 4) << 3);
    const int bn = nw + (lane & 7);
    const int bkoff = (((lane >> 3) & 1) << 3);

    // one-time per CTA: weight conversion + bias
    conv_weight(W_ih, sm + K1_WIH_HI, sm + K1_WIH_LO, tid, 256);
    float b4[4];
    b4[0] = b_ih[cA] + b_hh[cA];         b4[1] = b_ih[cA + 1] + b_hh[cA + 1];
    b4[2] = b_ih[cA + 8] + b_hh[cA + 8]; b4[3] = b_ih[cA + 9] + b_hh[cA + 9];
    __syncthreads();

    for (int tile = blockIdx.x; tile < K1_TILES; tile += gridDim.x) {
        const size_t rows0 = (size_t)tile * 64;

        // X tile: 64x128 fp32 -> split-bf16 swizzled
        {
            const float4* X4 = (const float4*)X;
#pragma unroll
            for (int j = 0; j < 8; j++) {
                int fi = tid + j * 256;               // 0..2047
                int r = fi >> 5, c4 = fi & 31;
                float4 x = X4[(rows0 + r) * 32 + c4];
                uint32_t h0 = packbf(x.x, x.y), h1 = packbf(x.z, x.w);
                float r0 = x.x - __uint_as_float(h0 << 16);
                float r1 = x.y - __uint_as_float(h0 & 0xffff0000u);
                float r2 = x.z - __uint_as_float(h1 << 16);
                float r3 = x.w - __uint_as_float(h1 & 0xffff0000u);
                uint32_t l0 = packbf(r0, r1), l1 = packbf(r2, r3);
                *(uint2*)(sm + K1_X_HI + hswz(r, c4 * 4)) = make_uint2(h0, h1);
                *(uint2*)(sm + K1_X_LO + hswz(r, c4 * 4)) = make_uint2(l0, l1);
            }
        }
        __syncthreads();

        float acc[4][2][4];
#pragma unroll
        for (int mt = 0; mt < 4; mt++)
#pragma unroll
            for (int nt = 0; nt < 2; nt++)
#pragma unroll
                for (int i = 0; i < 4; i++) acc[mt][nt][i] = 0.f;

#pragma unroll
        for (int k0 = 0; k0 < 8; k0++) {
            int bk = k0 * 16 + bkoff;
            uint32_t bh0[2], bh1[2], bl0[2], bl1[2];
            ldsm2(bh0, sb + K1_WIH_HI + hswz(bn, bk));
            ldsm2(bh1, sb + K1_WIH_HI + hswz(bn + 8, bk));
            ldsm2(bl0, sb + K1_WIH_LO + hswz(bn, bk));
            ldsm2(bl1, sb + K1_WIH_LO + hswz(bn + 8, bk));
            const int akb = akbase + k0 * 16;
#pragma unroll
            for (int mt = 0; mt < 4; mt++) {
                uint32_t xh[4], xl[4];
                ldsm4(xh, sb + K1_X_HI + hswz(mt * 16 + ar, akb));
                ldsm4(xl, sb + K1_X_LO + hswz(mt * 16 + ar, akb));
                mma_bf16(acc[mt][0], xh, bh0);
                mma_bf16(acc[mt][1], xh, bh1);
                mma_bf16(acc[mt][0], xh, bl0);
                mma_bf16(acc[mt][1], xh, bl1);
                mma_bf16(acc[mt][0], xl, bh0);
                mma_bf16(acc[mt][1], xl, bh1);
            }
        }
        __syncthreads();   // x tiles free -> stage overlay

#pragma unroll
        for (int mt = 0; mt < 4; mt++)
#pragma unroll
            for (int rh = 0; rh < 2; rh++) {
                int r = mt * 16 + g + rh * 8;
                *(float2*)(sm + K1_STAGE + r * 512 + cA * 4) =
                    make_float2(acc[mt][0][rh * 2] + b4[0], acc[mt][0][rh * 2 + 1] + b4[1]);
                *(float2*)(sm + K1_STAGE + r * 512 + (cA + 8) * 4) =
                    make_float2(acc[mt][1][rh * 2] + b4[2], acc[mt][1][rh * 2 + 1] + b4[3]);
            }
        __syncthreads();
        {
            float4* U4 = (float4*)g_U;
#pragma unroll
            for (int j = 0; j < 8; j++) {
                int fi = tid + j * 256;
                int r = fi >> 5, c4 = fi & 31;
                U4[(rows0 + r) * 32 + c4] = *(float4*)(sm + K1_STAGE + fi * 16);
            }
        }
        __syncthreads();   // stage region reused as X next tile
    }
}

// ===========================================================================
// Kernel 2: fused recurrence + LN + softmax-attention + dense head.
// 144 rows/CTA, grid 139 (one wave), 384 thr = 12 warps = wm3 x wn4 (n32).
// (byte-identical to the measured 252 us version)
// ===========================================================================
#define WHH_HI 0
#define WHH_LO 32768
#define H_HI   65536     /* 144 x 256 B */
#define H_LO   102400
#define UBUF   139264    /* 144 x 512 B fp32; OUTS overlay at the end */
#define RED_O  212992    /* float2 [4][144] */
#define LP_O   217600    /* float  [4][144] */
#define RAB_O  219904    /* float  [144] */
#define SCAL_O 220480    /* float[2] */
#define WGS_O  220488    /* float[10] */
#define WB_O   220528    /* float[10] */
#define K2_SMEM 220576

__global__ __launch_bounds__(384, 1) void rnn_fused(
    const float* __restrict__ W_hh,
    const float* __restrict__ ln_g,  const float* __restrict__ ln_b,
    const float* __restrict__ attn_W, const float* __restrict__ attn_b,
    const float* __restrict__ dense_W, const float* __restrict__ dense_b,
    float* __restrict__ out)
{
    extern __shared__ char sm[];
    const uint32_t sb = smem_u32_of(sm);
    const int tid = threadIdx.x, warp = tid >> 5, lane = tid & 31;
    const int g = lane >> 2, q4 = lane & 3;
    const int mgrp = warp >> 2;          // 0..2, rows [48*mgrp, +48)
    const int wnid = warp & 3;           // 0..3, cols [32*wnid, +32)
    const int nw = wnid * 32;
    const int rb = mgrp * 48;
    const int ar = lane & 15;
    const int akbase = ((lane >> 4) << 3);
    const int bnl = lane & 7;
    const int bksel = (((lane >> 3) & 1) << 3);
    const int n0 = blockIdx.x * 144;

    auto cpU = [&](int t) {
#pragma unroll
        for (int j = 0; j < 12; j++) {
            int fi = tid + j * 384;
            int r = fi >> 5, c4 = fi & 31;
            int gr = n0 + r; if (gr > NN - 1) gr = NN - 1;
            CP16(sb + UBUF + fi * 16, g_U + ((size_t)t * NN + gr) * 128 + c4 * 4);
        }
        CP_COMMIT();
    };
    cpU(0);

    conv_weight(W_hh, sm + WHH_HI, sm + WHH_LO, tid, 384);
    if (tid == 0) {
        float s1 = 0.f, s2 = 0.f;
        for (int c = 0; c < 128; c++) {
            s1 += attn_W[c] * ln_g[c];
            s2 += attn_W[c] * ln_b[c];
        }
        ((float*)(sm + SCAL_O))[0] = s1;
        ((float*)(sm + SCAL_O))[1] = s2 + attn_b[0];
    }
    if (tid >= 32 && tid < 32 + CC) {
        int c2 = tid - 32;
        float wg = 0.f, wb = 0.f;
        for (int k = 0; k < 128; k++) {
            float wd = dense_W[c2 * 128 + k];
            wg += wd * ln_g[k];
            wb += wd * ln_b[k];
        }
        ((float*)(sm + WGS_O))[c2] = wg;
        ((float*)(sm + WB_O))[c2] = wb;
    }

    float aw2[4][2];
#pragma unroll
    for (int nt = 0; nt < 4; nt++) {
        int c = nw + nt * 8 + q4 * 2;
        aw2[nt][0] = attn_W[c] * ln_g[c];
        aw2[nt][1] = attn_W[c + 1] * ln_g[c + 1];
    }

    CP_WAIT0();
    __syncthreads();
    const float S1 = ((float*)(sm + SCAL_O))[0];
    const float S2 = ((float*)(sm + SCAL_O))[1];

    // h0 = U[0] (biases folded in k1; no relu): pack into h tiles
#pragma unroll
    for (int mt = 0; mt < 3; mt++)
#pragma unroll
        for (int rh = 0; rh < 2; rh++) {
            int r = rb + mt * 16 + g + rh * 8;
#pragma unroll
            for (int nt = 0; nt < 4; nt++) {
                int c = nw + nt * 8 + q4 * 2;
                float2 u = *(float2*)(sm + UBUF + r * 512 + c * 4);
                uint32_t p0 = packbf(u.x, u.y);
                *(uint32_t*)(sm + H_HI + hswz(r, c)) = p0;
                uint32_t l0 = packbf(u.x - __uint_as_float(p0 << 16),
                                     u.y - __uint_as_float(p0 & 0xffff0000u));
                *(uint32_t*)(sm + H_LO + hswz(r, c)) = l0;
            }
        }
    __syncthreads();

    float P[3][4][4];
#pragma unroll
    for (int mt = 0; mt < 3; mt++)
#pragma unroll
        for (int nt = 0; nt < 4; nt++)
#pragma unroll
            for (int i = 0; i < 4; i++) P[mt][nt][i] = 0.f;
    float rs_s = 0.f, rs_q = 0.f;
    float acc[3][4][4];

    for (int t = 0; t < TT; t++) {
#pragma unroll
        for (int mt = 0; mt < 3; mt++)
#pragma unroll
            for (int nt = 0; nt < 4; nt++)
#pragma unroll
                for (int i = 0; i < 4; i++) acc[mt][nt][i] = 0.f;

        // acc = h @ Whh^T (3 split-bf16 products, n32 per warp)
#pragma unroll
        for (int k0 = 0; k0 < 8; k0++) {
            int bk = k0 * 16 + bksel;
            uint32_t bh[4][2], bl[4][2];
#pragma unroll
            for (int nt = 0; nt < 4; nt++) {
                ldsm2(bh[nt], sb + WHH_HI + hswz(nw + nt * 8 + bnl, bk));
                ldsm2(bl[nt], sb + WHH_LO + hswz(nw + nt * 8 + bnl, bk));
            }
            const int akb = akbase + k0 * 16;
#pragma unroll
            for (int mt = 0; mt < 3; mt++) {
                uint32_t hh[4], hl[4];
                ldsm4(hh, sb + H_HI + hswz(rb + mt * 16 + ar, akb));
                ldsm4(hl, sb + H_LO + hswz(rb + mt * 16 + ar, akb));
#pragma unroll
                for (int nt = 0; nt < 4; nt++) {
                    mma_bf16(acc[mt][nt], hh, bh[nt]);
                    mma_bf16(acc[mt][nt], hh, bl[nt]);
                    mma_bf16(acc[mt][nt], hl, bh[nt]);
                }
            }
        }
        CP_WAIT0();
        __syncthreads();

        // h_{t+1} = relu(acc + U); pack; LN/logit partials
#pragma unroll
        for (int mt = 0; mt < 3; mt++)
#pragma unroll
            for (int rh = 0; rh < 2; rh++) {
                int r = rb + mt * 16 + g + rh * 8;
                float s1 = 0.f, s2 = 0.f, lp = 0.f;
#pragma unroll
                for (int nt = 0; nt < 4; nt++) {
                    int c = nw + nt * 8 + q4 * 2;
                    float2 u = *(float2*)(sm + UBUF + r * 512 + c * 4);
                    float v0 = fmaxf(acc[mt][nt][rh * 2]     + u.x, 0.f);
                    float v1 = fmaxf(acc[mt][nt][rh * 2 + 1] + u.y, 0.f);
                    acc[mt][nt][rh * 2] = v0; acc[mt][nt][rh * 2 + 1] = v1;
                    uint32_t p0 = packbf(v0, v1);
                    *(uint32_t*)(sm + H_HI + hswz(r, c)) = p0;
                    uint32_t l0 = packbf(v0 - __uint_as_float(p0 << 16),
                                         v1 - __uint_as_float(p0 & 0xffff0000u));
                    *(uint32_t*)(sm + H_LO + hswz(r, c)) = l0;
                    s1 += v0 + v1;
                    s2 = fmaf(v0, v0, fmaf(v1, v1, s2));
                    lp = fmaf(v0, aw2[nt][0], fmaf(v1, aw2[nt][1], lp));
                }
                s1 += __shfl_xor_sync(0xffffffffu, s1, 1);
                s1 += __shfl_xor_sync(0xffffffffu, s1, 2);
                s2 += __shfl_xor_sync(0xffffffffu, s2, 1);
                s2 += __shfl_xor_sync(0xffffffffu, s2, 2);
                lp += __shfl_xor_sync(0xffffffffu, lp, 1);
                lp += __shfl_xor_sync(0xffffffffu, lp, 2);
                if (q4 == 0) {
                    *(float2*)(sm + RED_O + (wnid * 144 + r) * 8) = make_float2(s1, s2);
                    ((float*)(sm + LP_O))[wnid * 144 + r] = lp;
                }
            }
        __syncthreads();

        // per-row finalize -> w = exp(l)*rstd (max-free; logits bounded)
        if (tid < 144) {
            float s1 = 0.f, s2 = 0.f, lp = 0.f;
#pragma unroll
            for (int w = 0; w < 4; w++) {
                float2 v = *(float2*)(sm + RED_O + (w * 144 + tid) * 8);
                s1 += v.x; s2 += v.y;
                lp += ((float*)(sm + LP_O))[w * 144 + tid];
            }
            float mu = s1 * (1.0f / 128.0f);
            float var = fmaf(s2, 1.0f / 128.0f, -mu * mu);
            float rstd = rsqrtf(var + 1e-5f);
            float l = fmaf(rstd, lp - mu * S1, S2);
            float e = __expf(l);
            rs_s += e;
            float w = e * rstd;
            rs_q = fmaf(w, mu, rs_q);
            ((float*)(sm + RAB_O))[tid] = w;
        }
        __syncthreads();

        // P += w * h (acc holds h) ; prefetch U[t+1]
#pragma unroll
        for (int mt = 0; mt < 3; mt++)
#pragma unroll
            for (int rh = 0; rh < 2; rh++) {
                int r = rb + mt * 16 + g + rh * 8;
                float w = ((float*)(sm + RAB_O))[r];
#pragma unroll
                for (int nt = 0; nt < 4; nt++) {
                    P[mt][nt][rh * 2]     = fmaf(w, acc[mt][nt][rh * 2],     P[mt][nt][rh * 2]);
                    P[mt][nt][rh * 2 + 1] = fmaf(w, acc[mt][nt][rh * 2 + 1], P[mt][nt][rh * 2 + 1]);
                }
            }
        if (t < TT - 1) cpU(t + 1);
    }

    // ---- final: out = (Σ Wd·γ·P − q·Σ(Wd·γ))/s + Σ(Wd·β) + dense_b ----
    {
        float gl[4][2];
#pragma unroll
        for (int nt = 0; nt < 4; nt++) {
            int c = nw + nt * 8 + q4 * 2;
            gl[nt][0] = ln_g[c];
            gl[nt][1] = ln_g[c + 1];
        }
#pragma unroll
        for (int mt = 0; mt < 3; mt++)
#pragma unroll
            for (int rh = 0; rh < 2; rh++) {
                int r = rb + mt * 16 + g + rh * 8;
#pragma unroll
                for (int c2 = 0; c2 < CC; c2++) {
                    float s = 0.f;
#pragma unroll
                    for (int nt = 0; nt < 4; nt++) {
                        int c = nw + nt * 8 + q4 * 2;
                        s = fmaf(P[mt][nt][rh * 2],     dense_W[c2 * 128 + c] * gl[nt][0], s);
                        s = fmaf(P[mt][nt][rh * 2 + 1], dense_W[c2 * 128 + c + 1] * gl[nt][1], s);
                    }
                    s += __shfl_xor_sync(0xffffffffu, s, 1);
                    s += __shfl_xor_sync(0xffffffffu, s, 2);
                    if (q4 == 0)
                        ((float*)(sm + UBUF))[(wnid * 144 + r) * CC + c2] = s;
                }
            }
    }
    __syncthreads();
    if (tid < 144 && (n0 + tid) < NN) {
        float inv = 1.0f / rs_s;
#pragma unroll
        for (int c2 = 0; c2 < CC; c2++) {
            float tot = 0.f;
#pragma unroll
            for (int w = 0; w < 4; w++)
                tot += ((float*)(sm + UBUF))[(w * 144 + tid) * CC + c2];
            float val = (tot - rs_q * ((float*)(sm + WGS_O))[c2]) * inv
                        + ((float*)(sm + WB_O))[c2] + dense_b[c2];
            out[(n0 + tid) * CC + c2] = val;
        }
    }
}

// ===========================================================================
extern "C" void kernel_launch(void* const* d_in, const int* in_sizes, int n_in,
                              void* d_out, int out_size)
{
    const float* X       = (const float*)d_in[0];
    const float* W_ih    = (const float*)d_in[1];
    const float* W_hh    = (const float*)d_in[2];
    const float* b_ih    = (const float*)d_in[3];
    const float* b_hh    = (const float*)d_in[4];
    const float* ln_g    = (const float*)d_in[5];
    const float* ln_b    = (const float*)d_in[6];
    const float* attn_W  = (const float*)d_in[7];
    const float* attn_b  = (const float*)d_in[8];
    const float* dense_W = (const float*)d_in[9];
    const float* dense_b = (const float*)d_in[10];
    float* out = (float*)d_out;

    cudaFuncSetAttribute(u_gemm, cudaFuncAttributeMaxDynamicSharedMemorySize, K1_SMEM);
    cudaFuncSetAttribute(rnn_fused, cudaFuncAttributeMaxDynamicSharedMemorySize, K2_SMEM);

    u_gemm<<<296, 256, K1_SMEM>>>(X, W_ih, b_ih, b_hh);
    rnn_fused<<<(NN + 143) / 144, 384, K2_SMEM>>>(W_hh, ln_g, ln_b, attn_W, attn_b,
                                                  dense_W, dense_b, out);
}

// round 12
// speedup vs baseline: 1.2854x; 1.0043x over previous
#include <cuda_runtime.h>
#include <cuda_bf16.h>
#include <cstdint>

#define TT 32
#define NN 20000
#define CC 10

// Scratch: U[t][n][c] = X[t,n,:]@W_ih^T + b_ih + b_hh  (fp32, 327.68 MB)
__device__ float g_U[(size_t)TT * NN * 128];

// ---------------------------------------------------------------------------
__device__ __forceinline__ uint32_t smem_u32_of(const void* p) {
    uint32_t a;
    asm("{ .reg .u64 t; cvta.to.shared.u64 t, %1; cvt.u32.u64 %0, t; }" : "=r"(a) : "l"(p));
    return a;
}
__device__ __forceinline__ void mma_bf16(float* c, const uint32_t* a, const uint32_t* b) {
    asm volatile("mma.sync.aligned.m16n8k16.row.col.f32.bf16.bf16.f32 "
        "{%0,%1,%2,%3}, {%4,%5,%6,%7}, {%8,%9}, {%0,%1,%2,%3};"
        : "+f"(c[0]), "+f"(c[1]), "+f"(c[2]), "+f"(c[3])
        : "r"(a[0]), "r"(a[1]), "r"(a[2]), "r"(a[3]), "r"(b[0]), "r"(b[1]));
}
__device__ __forceinline__ void ldsm4(uint32_t* r, uint32_t addr) {
    asm volatile("ldmatrix.sync.aligned.m8n8.x4.shared.b16 {%0,%1,%2,%3}, [%4];"
        : "=r"(r[0]), "=r"(r[1]), "=r"(r[2]), "=r"(r[3]) : "r"(addr));
}
__device__ __forceinline__ void ldsm2(uint32_t* r, uint32_t addr) {
    asm volatile("ldmatrix.sync.aligned.m8n8.x2.shared.b16 {%0,%1}, [%2];"
        : "=r"(r[0]), "=r"(r[1]) : "r"(addr));
}
// swizzled byte offset in a [rows][128] bf16 tile (256 B/row)
__device__ __forceinline__ uint32_t hswz(int r, int k) {
    int k8 = k >> 3;
    int s = (k8 & 8) | ((k8 ^ r) & 7);
    return (uint32_t)(r * 256 + s * 16 + (k & 7) * 2);
}
__device__ __forceinline__ uint32_t packbf(float a, float b) {
    uint32_t p;
    asm("cvt.rn.bf16x2.f32 %0, %1, %2;" : "=r"(p) : "f"(b), "f"(a));
    return p;
}
__device__ __forceinline__ void conv_weight(const float* __restrict__ W,
                                            char* hi, char* lo, int tid, int nthr) {
    for (int idx = tid; idx < 16384; idx += nthr) {
        int r = idx >> 7, k = idx & 127;
        float w = W[idx];
        __nv_bfloat16 wh = __float2bfloat16(w);
        uint32_t o = hswz(r, k);
        *(__nv_bfloat16*)(hi + o) = wh;
        *(__nv_bfloat16*)(lo + o) = __float2bfloat16(w - __bfloat162float(wh));
    }
}
#define CP16(dst, src) asm volatile("cp.async.cg.shared.global [%0], [%1], 16;" :: "r"(dst), "l"(src))
#define CP_COMMIT()    asm volatile("cp.async.commit_group;" ::: "memory")
#define CP_WAIT0()     asm volatile("cp.async.wait_group 0;" ::: "memory")

// ===========================================================================
// Kernel 1 (persistent, software-pipelined): U = X@Wih^T + (b_ih+b_hh).
// Grid 296 (occ 2). X for tile i+1 prefetched into registers while tile i
// runs mma/stage/store, hiding the LDG latency.
// ===========================================================================
#define K1_WIH_HI 0
#define K1_WIH_LO 32768
#define K1_X_HI   65536     /* 64 x 256 B */
#define K1_X_LO   81920
#define K1_STAGE  65536     /* overlay after mma: 64 x 512 B fp32 */
#define K1_SMEM   98304
#define K1_TILES  ((TT * NN) / 64)   /* 10000 */
#define K1_GRID   296

__global__ __launch_bounds__(256, 2) void u_gemm(
    const float* __restrict__ X,
    const float* __restrict__ W_ih,
    const float* __restrict__ b_ih,
    const float* __restrict__ b_hh)
{
    extern __shared__ char sm[];
    const uint32_t sb = smem_u32_of(sm);
    const int tid = threadIdx.x, warp = tid >> 5, lane = tid & 31;
    const int g = lane >> 2, q4 = lane & 3;
    const int nw = warp * 16;
    const int cA = nw + q4 * 2;
    const int ar = lane & 15;
    const int akbase = ((lane >> 4) << 3);
    const int bn = nw + (lane & 7);
    const int bkoff = (((lane >> 3) & 1) << 3);

    // one-time per CTA: weight conversion + bias
    conv_weight(W_ih, sm + K1_WIH_HI, sm + K1_WIH_LO, tid, 256);
    float b4[4];
    b4[0] = b_ih[cA] + b_hh[cA];         b4[1] = b_ih[cA + 1] + b_hh[cA + 1];
    b4[2] = b_ih[cA + 8] + b_hh[cA + 8]; b4[3] = b_ih[cA + 9] + b_hh[cA + 9];

    const float4* X4 = (const float4*)X;
    float4 xr[8];
    auto ldg_tile = [&](int tl) {
        const size_t rows0 = (size_t)tl * 64;
#pragma unroll
        for (int j = 0; j < 8; j++) {
            int fi = tid + j * 256;               // 0..2047
            int r = fi >> 5, c4 = fi & 31;
            xr[j] = X4[(rows0 + r) * 32 + c4];
        }
    };

    ldg_tile(blockIdx.x);        // prefetch first tile (overlaps conv_weight tail)
    __syncthreads();             // W tiles ready

    for (int tile = blockIdx.x; tile < K1_TILES; tile += K1_GRID) {
        // convert xr -> split-bf16 swizzled X tiles
#pragma unroll
        for (int j = 0; j < 8; j++) {
            int fi = tid + j * 256;
            int r = fi >> 5, c4 = fi & 31;
            float4 x = xr[j];
            uint32_t h0 = packbf(x.x, x.y), h1 = packbf(x.z, x.w);
            float r0 = x.x - __uint_as_float(h0 << 16);
            float r1 = x.y - __uint_as_float(h0 & 0xffff0000u);
            float r2 = x.z - __uint_as_float(h1 << 16);
            float r3 = x.w - __uint_as_float(h1 & 0xffff0000u);
            uint32_t l0 = packbf(r0, r1), l1 = packbf(r2, r3);
            *(uint2*)(sm + K1_X_HI + hswz(r, c4 * 4)) = make_uint2(h0, h1);
            *(uint2*)(sm + K1_X_LO + hswz(r, c4 * 4)) = make_uint2(l0, l1);
        }
        __syncthreads();

        // prefetch next tile's X into registers (latency hidden by mma+store)
        if (tile + K1_GRID < K1_TILES) ldg_tile(tile + K1_GRID);

        float acc[4][2][4];
#pragma unroll
        for (int mt = 0; mt < 4; mt++)
#pragma unroll
            for (int nt = 0; nt < 2; nt++)
#pragma unroll
                for (int i = 0; i < 4; i++) acc[mt][nt][i] = 0.f;

#pragma unroll
        for (int k0 = 0; k0 < 8; k0++) {
            int bk = k0 * 16 + bkoff;
            uint32_t bh0[2], bh1[2], bl0[2], bl1[2];
            ldsm2(bh0, sb + K1_WIH_HI + hswz(bn, bk));
            ldsm2(bh1, sb + K1_WIH_HI + hswz(bn + 8, bk));
            ldsm2(bl0, sb + K1_WIH_LO + hswz(bn, bk));
            ldsm2(bl1, sb + K1_WIH_LO + hswz(bn + 8, bk));
            const int akb = akbase + k0 * 16;
#pragma unroll
            for (int mt = 0; mt < 4; mt++) {
                uint32_t xh[4], xl[4];
                ldsm4(xh, sb + K1_X_HI + hswz(mt * 16 + ar, akb));
                ldsm4(xl, sb + K1_X_LO + hswz(mt * 16 + ar, akb));
                mma_bf16(acc[mt][0], xh, bh0);
                mma_bf16(acc[mt][1], xh, bh1);
                mma_bf16(acc[mt][0], xh, bl0);
                mma_bf16(acc[mt][1], xh, bl1);
                mma_bf16(acc[mt][0], xl, bh0);
                mma_bf16(acc[mt][1], xl, bh1);
            }
        }
        __syncthreads();   // x tiles free -> stage overlay

#pragma unroll
        for (int mt = 0; mt < 4; mt++)
#pragma unroll
            for (int rh = 0; rh < 2; rh++) {
                int r = mt * 16 + g + rh * 8;
                *(float2*)(sm + K1_STAGE + r * 512 + cA * 4) =
                    make_float2(acc[mt][0][rh * 2] + b4[0], acc[mt][0][rh * 2 + 1] + b4[1]);
                *(float2*)(sm + K1_STAGE + r * 512 + (cA + 8) * 4) =
                    make_float2(acc[mt][1][rh * 2] + b4[2], acc[mt][1][rh * 2 + 1] + b4[3]);
            }
        __syncthreads();
        {
            const size_t rows0 = (size_t)tile * 64;
            float4* U4 = (float4*)g_U;
#pragma unroll
            for (int j = 0; j < 8; j++) {
                int fi = tid + j * 256;
                int r = fi >> 5, c4 = fi & 31;
                U4[(rows0 + r) * 32 + c4] = *(float4*)(sm + K1_STAGE + fi * 16);
            }
        }
        __syncthreads();   // stage region reused as X next tile
    }
}

// ===========================================================================
// Kernel 2: fused recurrence + LN + softmax-attention + dense head.
// 144 rows/CTA, grid 139 (one wave), 384 thr = 12 warps = wm3 x wn4 (n32).
// (byte-identical to the measured 251 us version)
// ===========================================================================
#define WHH_HI 0
#define WHH_LO 32768
#define H_HI   65536     /* 144 x 256 B */
#define H_LO   102400
#define UBUF   139264    /* 144 x 512 B fp32; OUTS overlay at the end */
#define RED_O  212992    /* float2 [4][144] */
#define LP_O   217600    /* float  [4][144] */
#define RAB_O  219904    /* float  [144] */
#define SCAL_O 220480    /* float[2] */
#define WGS_O  220488    /* float[10] */
#define WB_O   220528    /* float[10] */
#define K2_SMEM 220576

__global__ __launch_bounds__(384, 1) void rnn_fused(
    const float* __restrict__ W_hh,
    const float* __restrict__ ln_g,  const float* __restrict__ ln_b,
    const float* __restrict__ attn_W, const float* __restrict__ attn_b,
    const float* __restrict__ dense_W, const float* __restrict__ dense_b,
    float* __restrict__ out)
{
    extern __shared__ char sm[];
    const uint32_t sb = smem_u32_of(sm);
    const int tid = threadIdx.x, warp = tid >> 5, lane = tid & 31;
    const int g = lane >> 2, q4 = lane & 3;
    const int mgrp = warp >> 2;          // 0..2, rows [48*mgrp, +48)
    const int wnid = warp & 3;           // 0..3, cols [32*wnid, +32)
    const int nw = wnid * 32;
    const int rb = mgrp * 48;
    const int ar = lane & 15;
    const int akbase = ((lane >> 4) << 3);
    const int bnl = lane & 7;
    const int bksel = (((lane >> 3) & 1) << 3);
    const int n0 = blockIdx.x * 144;

    auto cpU = [&](int t) {
#pragma unroll
        for (int j = 0; j < 12; j++) {
            int fi = tid + j * 384;
            int r = fi >> 5, c4 = fi & 31;
            int gr = n0 + r; if (gr > NN - 1) gr = NN - 1;
            CP16(sb + UBUF + fi * 16, g_U + ((size_t)t * NN + gr) * 128 + c4 * 4);
        }
        CP_COMMIT();
    };
    cpU(0);

    conv_weight(W_hh, sm + WHH_HI, sm + WHH_LO, tid, 384);
    if (tid == 0) {
        float s1 = 0.f, s2 = 0.f;
        for (int c = 0; c < 128; c++) {
            s1 += attn_W[c] * ln_g[c];
            s2 += attn_W[c] * ln_b[c];
        }
        ((float*)(sm + SCAL_O))[0] = s1;
        ((float*)(sm + SCAL_O))[1] = s2 + attn_b[0];
    }
    if (tid >= 32 && tid < 32 + CC) {
        int c2 = tid - 32;
        float wg = 0.f, wb = 0.f;
        for (int k = 0; k < 128; k++) {
            float wd = dense_W[c2 * 128 + k];
            wg += wd * ln_g[k];
            wb += wd * ln_b[k];
        }
        ((float*)(sm + WGS_O))[c2] = wg;
        ((float*)(sm + WB_O))[c2] = wb;
    }

    float aw2[4][2];
#pragma unroll
    for (int nt = 0; nt < 4; nt++) {
        int c = nw + nt * 8 + q4 * 2;
        aw2[nt][0] = attn_W[c] * ln_g[c];
        aw2[nt][1] = attn_W[c + 1] * ln_g[c + 1];
    }

    CP_WAIT0();
    __syncthreads();
    const float S1 = ((float*)(sm + SCAL_O))[0];
    const float S2 = ((float*)(sm + SCAL_O))[1];

    // h0 = U[0] (biases folded in k1; no relu): pack into h tiles
#pragma unroll
    for (int mt = 0; mt < 3; mt++)
#pragma unroll
        for (int rh = 0; rh < 2; rh++) {
            int r = rb + mt * 16 + g + rh * 8;
#pragma unroll
            for (int nt = 0; nt < 4; nt++) {
                int c = nw + nt * 8 + q4 * 2;
                float2 u = *(float2*)(sm + UBUF + r * 512 + c * 4);
                uint32_t p0 = packbf(u.x, u.y);
                *(uint32_t*)(sm + H_HI + hswz(r, c)) = p0;
                uint32_t l0 = packbf(u.x - __uint_as_float(p0 << 16),
                                     u.y - __uint_as_float(p0 & 0xffff0000u));
                *(uint32_t*)(sm + H_LO + hswz(r, c)) = l0;
            }
        }
    __syncthreads();

    float P[3][4][4];
#pragma unroll
    for (int mt = 0; mt < 3; mt++)
#pragma unroll
        for (int nt = 0; nt < 4; nt++)
#pragma unroll
            for (int i = 0; i < 4; i++) P[mt][nt][i] = 0.f;
    float rs_s = 0.f, rs_q = 0.f;
    float acc[3][4][4];

    for (int t = 0; t < TT; t++) {
#pragma unroll
        for (int mt = 0; mt < 3; mt++)
#pragma unroll
            for (int nt = 0; nt < 4; nt++)
#pragma unroll
                for (int i = 0; i < 4; i++) acc[mt][nt][i] = 0.f;

        // acc = h @ Whh^T (3 split-bf16 products, n32 per warp)
#pragma unroll
        for (int k0 = 0; k0 < 8; k0++) {
            int bk = k0 * 16 + bksel;
            uint32_t bh[4][2], bl[4][2];
#pragma unroll
            for (int nt = 0; nt < 4; nt++) {
                ldsm2(bh[nt], sb + WHH_HI + hswz(nw + nt * 8 + bnl, bk));
                ldsm2(bl[nt], sb + WHH_LO + hswz(nw + nt * 8 + bnl, bk));
            }
            const int akb = akbase + k0 * 16;
#pragma unroll
            for (int mt = 0; mt < 3; mt++) {
                uint32_t hh[4], hl[4];
                ldsm4(hh, sb + H_HI + hswz(rb + mt * 16 + ar, akb));
                ldsm4(hl, sb + H_LO + hswz(rb + mt * 16 + ar, akb));
#pragma unroll
                for (int nt = 0; nt < 4; nt++) {
                    mma_bf16(acc[mt][nt], hh, bh[nt]);
                    mma_bf16(acc[mt][nt], hh, bl[nt]);
                    mma_bf16(acc[mt][nt], hl, bh[nt]);
                }
            }
        }
        CP_WAIT0();
        __syncthreads();

        // h_{t+1} = relu(acc + U); pack; LN/logit partials
#pragma unroll
        for (int mt = 0; mt < 3; mt++)
#pragma unroll
            for (int rh = 0; rh < 2; rh++) {
                int r = rb + mt * 16 + g + rh * 8;
                float s1 = 0.f, s2 = 0.f, lp = 0.f;
#pragma unroll
                for (int nt = 0; nt < 4; nt++) {
                    int c = nw + nt * 8 + q4 * 2;
                    float2 u = *(float2*)(sm + UBUF + r * 512 + c * 4);
                    float v0 = fmaxf(acc[mt][nt][rh * 2]     + u.x, 0.f);
                    float v1 = fmaxf(acc[mt][nt][rh * 2 + 1] + u.y, 0.f);
                    acc[mt][nt][rh * 2] = v0; acc[mt][nt][rh * 2 + 1] = v1;
                    uint32_t p0 = packbf(v0, v1);
                    *(uint32_t*)(sm + H_HI + hswz(r, c)) = p0;
                    uint32_t l0 = packbf(v0 - __uint_as_float(p0 << 16),
                                         v1 - __uint_as_float(p0 & 0xffff0000u));
                    *(uint32_t*)(sm + H_LO + hswz(r, c)) = l0;
                    s1 += v0 + v1;
                    s2 = fmaf(v0, v0, fmaf(v1, v1, s2));
                    lp = fmaf(v0, aw2[nt][0], fmaf(v1, aw2[nt][1], lp));
                }
                s1 += __shfl_xor_sync(0xffffffffu, s1, 1);
                s1 += __shfl_xor_sync(0xffffffffu, s1, 2);
                s2 += __shfl_xor_sync(0xffffffffu, s2, 1);
                s2 += __shfl_xor_sync(0xffffffffu, s2, 2);
                lp += __shfl_xor_sync(0xffffffffu, lp, 1);
                lp += __shfl_xor_sync(0xffffffffu, lp, 2);
                if (q4 == 0) {
                    *(float2*)(sm + RED_O + (wnid * 144 + r) * 8) = make_float2(s1, s2);
                    ((float*)(sm + LP_O))[wnid * 144 + r] = lp;
                }
            }
        __syncthreads();

        // per-row finalize -> w = exp(l)*rstd (max-free; logits bounded)
        if (tid < 144) {
            float s1 = 0.f, s2 = 0.f, lp = 0.f;
#pragma unroll
            for (int w = 0; w < 4; w++) {
                float2 v = *(float2*)(sm + RED_O + (w * 144 + tid) * 8);
                s1 += v.x; s2 += v.y;
                lp += ((float*)(sm + LP_O))[w * 144 + tid];
            }
            float mu = s1 * (1.0f / 128.0f);
            float var = fmaf(s2, 1.0f / 128.0f, -mu * mu);
            float rstd = rsqrtf(var + 1e-5f);
            float l = fmaf(rstd, lp - mu * S1, S2);
            float e = __expf(l);
            rs_s += e;
            float w = e * rstd;
            rs_q = fmaf(w, mu, rs_q);
            ((float*)(sm + RAB_O))[tid] = w;
        }
        __syncthreads();

        // P += w * h (acc holds h) ; prefetch U[t+1]
#pragma unroll
        for (int mt = 0; mt < 3; mt++)
#pragma unroll
            for (int rh = 0; rh < 2; rh++) {
                int r = rb + mt * 16 + g + rh * 8;
                float w = ((float*)(sm + RAB_O))[r];
#pragma unroll
                for (int nt = 0; nt < 4; nt++) {
                    P[mt][nt][rh * 2]     = fmaf(w, acc[mt][nt][rh * 2],     P[mt][nt][rh * 2]);
                    P[mt][nt][rh * 2 + 1] = fmaf(w, acc[mt][nt][rh * 2 + 1], P[mt][nt][rh * 2 + 1]);
                }
            }
        if (t < TT - 1) cpU(t + 1);
    }

    // ---- final: out = (Σ Wd·γ·P − q·Σ(Wd·γ))/s + Σ(Wd·β) + dense_b ----
    {
        float gl[4][2];
#pragma unroll
        for (int nt = 0; nt < 4; nt++) {
            int c = nw + nt * 8 + q4 * 2;
            gl[nt][0] = ln_g[c];
            gl[nt][1] = ln_g[c + 1];
        }
#pragma unroll
        for (int mt = 0; mt < 3; mt++)
#pragma unroll
            for (int rh = 0; rh < 2; rh++) {
                int r = rb + mt * 16 + g + rh * 8;
#pragma unroll
                for (int c2 = 0; c2 < CC; c2++) {
                    float s = 0.f;
#pragma unroll
                    for (int nt = 0; nt < 4; nt++) {
                        int c = nw + nt * 8 + q4 * 2;
                        s = fmaf(P[mt][nt][rh * 2],     dense_W[c2 * 128 + c] * gl[nt][0], s);
                        s = fmaf(P[mt][nt][rh * 2 + 1], dense_W[c2 * 128 + c + 1] * gl[nt][1], s);
                    }
                    s += __shfl_xor_sync(0xffffffffu, s, 1);
                    s += __shfl_xor_sync(0xffffffffu, s, 2);
                    if (q4 == 0)
                        ((float*)(sm + UBUF))[(wnid * 144 + r) * CC + c2] = s;
                }
            }
    }
    __syncthreads();
    if (tid < 144 && (n0 + tid) < NN) {
        float inv = 1.0f / rs_s;
#pragma unroll
        for (int c2 = 0; c2 < CC; c2++) {
            float tot = 0.f;
#pragma unroll
            for (int w = 0; w < 4; w++)
                tot += ((float*)(sm + UBUF))[(w * 144 + tid) * CC + c2];
            float val = (tot - rs_q * ((float*)(sm + WGS_O))[c2]) * inv
                        + ((float*)(sm + WB_O))[c2] + dense_b[c2];
            out[(n0 + tid) * CC + c2] = val;
        }
    }
}

// ===========================================================================
extern "C" void kernel_launch(void* const* d_in, const int* in_sizes, int n_in,
                              void* d_out, int out_size)
{
    const float* X       = (const float*)d_in[0];
    const float* W_ih    = (const float*)d_in[1];
    const float* W_hh    = (const float*)d_in[2];
    const float* b_ih    = (const float*)d_in[3];
    const float* b_hh    = (const float*)d_in[4];
    const float* ln_g    = (const float*)d_in[5];
    const float* ln_b    = (const float*)d_in[6];
    const float* attn_W  = (const float*)d_in[7];
    const float* attn_b  = (const float*)d_in[8];
    const float* dense_W = (const float*)d_in[9];
    const float* dense_b = (const float*)d_in[10];
    float* out = (float*)d_out;

    cudaFuncSetAttribute(u_gemm, cudaFuncAttributeMaxDynamicSharedMemorySize, K1_SMEM);
    cudaFuncSetAttribute(rnn_fused, cudaFuncAttributeMaxDynamicSharedMemorySize, K2_SMEM);

    u_gemm<<<K1_GRID, 256, K1_SMEM>>>(X, W_ih, b_ih, b_hh);
    rnn_fused<<<(NN + 143) / 144, 384, K2_SMEM>>>(W_hh, ln_g, ln_b, attn_W, attn_b,
                                                  dense_W, dense_b, out);
}

// round 14
// speedup vs baseline: 1.3688x; 1.0649x over previous
#include <cuda_runtime.h>
#include <cuda_bf16.h>
#include <cstdint>

#define TT 32
#define NN 20000
#define CC 10

// Scratch: U[t][n][c] = X[t,n,:]@W_ih^T + b_ih + b_hh  (fp32, 327.68 MB)
__device__ float g_U[(size_t)TT * NN * 128];

// ---------------------------------------------------------------------------
__device__ __forceinline__ uint32_t smem_u32_of(const void* p) {
    uint32_t a;
    asm("{ .reg .u64 t; cvta.to.shared.u64 t, %1; cvt.u32.u64 %0, t; }" : "=r"(a) : "l"(p));
    return a;
}
__device__ __forceinline__ void mma_bf16(float* c, const uint32_t* a, const uint32_t* b) {
    asm volatile("mma.sync.aligned.m16n8k16.row.col.f32.bf16.bf16.f32 "
        "{%0,%1,%2,%3}, {%4,%5,%6,%7}, {%8,%9}, {%0,%1,%2,%3};"
        : "+f"(c[0]), "+f"(c[1]), "+f"(c[2]), "+f"(c[3])
        : "r"(a[0]), "r"(a[1]), "r"(a[2]), "r"(a[3]), "r"(b[0]), "r"(b[1]));
}
__device__ __forceinline__ void ldsm4(uint32_t* r, uint32_t addr) {
    asm volatile("ldmatrix.sync.aligned.m8n8.x4.shared.b16 {%0,%1,%2,%3}, [%4];"
        : "=r"(r[0]), "=r"(r[1]), "=r"(r[2]), "=r"(r[3]) : "r"(addr));
}
__device__ __forceinline__ void ldsm2(uint32_t* r, uint32_t addr) {
    asm volatile("ldmatrix.sync.aligned.m8n8.x2.shared.b16 {%0,%1}, [%2];"
        : "=r"(r[0]), "=r"(r[1]) : "r"(addr));
}
// swizzled byte offset in a [rows][128] bf16 tile (256 B/row)
__device__ __forceinline__ uint32_t hswz(int r, int k) {
    int k8 = k >> 3;
    int s = (k8 & 8) | ((k8 ^ r) & 7);
    return (uint32_t)(r * 256 + s * 16 + (k & 7) * 2);
}
__device__ __forceinline__ uint32_t packbf(float a, float b) {
    uint32_t p;
    asm("cvt.rn.bf16x2.f32 %0, %1, %2;" : "=r"(p) : "f"(b), "f"(a));
    return p;
}
__device__ __forceinline__ void conv_weight(const float* __restrict__ W,
                                            char* hi, char* lo, int tid, int nthr) {
    for (int idx = tid; idx < 16384; idx += nthr) {
        int r = idx >> 7, k = idx & 127;
        float w = W[idx];
        __nv_bfloat16 wh = __float2bfloat16(w);
        uint32_t o = hswz(r, k);
        *(__nv_bfloat16*)(hi + o) = wh;
        *(__nv_bfloat16*)(lo + o) = __float2bfloat16(w - __bfloat162float(wh));
    }
}
#define CP16(dst, src) asm volatile("cp.async.cg.shared.global [%0], [%1], 16;" :: "r"(dst), "l"(src))
#define CP_COMMIT()    asm volatile("cp.async.commit_group;" ::: "memory")
#define CP_WAIT0()     asm volatile("cp.async.wait_group 0;" ::: "memory")

// ===========================================================================
// Kernel 1 (persistent, cp.async staged): U = X@Wih^T + (b_ih+b_hh).
// Grid 296 (occ 2), 32-row tiles (20000 total). X[i+1] lands in SMEM fp32 via
// cp.async while tile i runs mma + direct-STG store. Two barriers per tile.
// ===========================================================================
#define K1_WIH_HI 0
#define K1_WIH_LO 32768
#define K1_XBF_HI 65536     /* 32 x 256 B */
#define K1_XBF_LO 73728
#define K1_XF32   81920     /* 32 x 512 B fp32 cp.async landing */
#define K1_SMEM   98304
#define K1_TILES  20000
#define K1_GRID   296

__global__ __launch_bounds__(256, 2) void u_gemm(
    const float* __restrict__ X,
    const float* __restrict__ W_ih,
    const float* __restrict__ b_ih,
    const float* __restrict__ b_hh)
{
    extern __shared__ char sm[];
    const uint32_t sb = smem_u32_of(sm);
    const int tid = threadIdx.x, warp = tid >> 5, lane = tid & 31;
    const int g = lane >> 2, q4 = lane & 3;
    const int nw = warp * 16;
    const int cA = nw + q4 * 2;
    const int ar = lane & 15;
    const int akbase = ((lane >> 4) << 3);
    const int bn = nw + (lane & 7);
    const int bkoff = (((lane >> 3) & 1) << 3);

    // cp.async one 32x128 fp32 X tile -> XF32 (1024 16B chunks, 4/thread)
    auto cp_x = [&](int tl) {
#pragma unroll
        for (int j = 0; j < 4; j++) {
            int fi = tid + j * 256;               // 0..1023
            CP16(sb + K1_XF32 + fi * 16, X + (size_t)tl * 4096 + fi * 4);
        }
        CP_COMMIT();
    };

    cp_x(blockIdx.x);   // first tile in flight during weight conversion

    conv_weight(W_ih, sm + K1_WIH_HI, sm + K1_WIH_LO, tid, 256);
    float b4[4];
    b4[0] = b_ih[cA] + b_hh[cA];         b4[1] = b_ih[cA + 1] + b_hh[cA + 1];
    b4[2] = b_ih[cA + 8] + b_hh[cA + 8]; b4[3] = b_ih[cA + 9] + b_hh[cA + 9];

    CP_WAIT0();
    __syncthreads();     // W tiles + X[tile0] ready

    for (int tile = blockIdx.x; tile < K1_TILES; tile += K1_GRID) {
        // convert XF32 -> split-bf16 swizzled XBF (4 float4 per thread)
#pragma unroll
        for (int j = 0; j < 4; j++) {
            int fi = tid + j * 256;
            int r = fi >> 5, c4 = fi & 31;
            float4 x = *(const float4*)(sm + K1_XF32 + fi * 16);
            uint32_t h0 = packbf(x.x, x.y), h1 = packbf(x.z, x.w);
            float r0 = x.x - __uint_as_float(h0 << 16);
            float r1 = x.y - __uint_as_float(h0 & 0xffff0000u);
            float r2 = x.z - __uint_as_float(h1 << 16);
            float r3 = x.w - __uint_as_float(h1 & 0xffff0000u);
            uint32_t l0 = packbf(r0, r1), l1 = packbf(r2, r3);
            *(uint2*)(sm + K1_XBF_HI + hswz(r, c4 * 4)) = make_uint2(h0, h1);
            *(uint2*)(sm + K1_XBF_LO + hswz(r, c4 * 4)) = make_uint2(l0, l1);
        }
        __syncthreads();   // XBF ready; XF32 fully consumed

        // next tile's X starts landing while mma + store run
        if (tile + K1_GRID < K1_TILES) cp_x(tile + K1_GRID);

        float acc[2][2][4];
#pragma unroll
        for (int mt = 0; mt < 2; mt++)
#pragma unroll
            for (int nt = 0; nt < 2; nt++)
#pragma unroll
                for (int i = 0; i < 4; i++) acc[mt][nt][i] = 0.f;

#pragma unroll
        for (int k0 = 0; k0 < 8; k0++) {
            int bk = k0 * 16 + bkoff;
            uint32_t bh0[2], bh1[2], bl0[2], bl1[2];
            ldsm2(bh0, sb + K1_WIH_HI + hswz(bn, bk));
            ldsm2(bh1, sb + K1_WIH_HI + hswz(bn + 8, bk));
            ldsm2(bl0, sb + K1_WIH_LO + hswz(bn, bk));
            ldsm2(bl1, sb + K1_WIH_LO + hswz(bn + 8, bk));
            const int akb = akbase + k0 * 16;
#pragma unroll
            for (int mt = 0; mt < 2; mt++) {
                uint32_t xh[4], xl[4];
                ldsm4(xh, sb + K1_XBF_HI + hswz(mt * 16 + ar, akb));
                ldsm4(xl, sb + K1_XBF_LO + hswz(mt * 16 + ar, akb));
                mma_bf16(acc[mt][0], xh, bh0);
                mma_bf16(acc[mt][1], xh, bh1);
                mma_bf16(acc[mt][0], xh, bl0);
                mma_bf16(acc[mt][1], xh, bl1);
                mma_bf16(acc[mt][0], xl, bh0);
                mma_bf16(acc[mt][1], xl, bh1);
            }
        }

        // direct store U from accumulators (+bias); 32B runs per 4 lanes
        {
            float* Ur = g_U + (size_t)tile * 4096;
#pragma unroll
            for (int mt = 0; mt < 2; mt++)
#pragma unroll
                for (int rh = 0; rh < 2; rh++) {
                    int r = mt * 16 + g + rh * 8;
                    *(float2*)(Ur + r * 128 + cA) =
                        make_float2(acc[mt][0][rh * 2] + b4[0],
                                    acc[mt][0][rh * 2 + 1] + b4[1]);
                    *(float2*)(Ur + r * 128 + cA + 8) =
                        make_float2(acc[mt][1][rh * 2] + b4[2],
                                    acc[mt][1][rh * 2 + 1] + b4[3]);
                }
        }

        CP_WAIT0();        // next X landed
        __syncthreads();   // all mma reads of XBF done -> convert may rewrite
    }
}

// ===========================================================================
// Kernel 2: fused recurrence + LN + softmax-attention + dense head.
// 144 rows/CTA, grid 139 (one wave), 384 thr = 12 warps = wm3 x wn4 (n32).
// (byte-identical to the measured 251.8 us version)
// ===========================================================================
#define WHH_HI 0
#define WHH_LO 32768
#define H_HI   65536     /* 144 x 256 B */
#define H_LO   102400
#define UBUF   139264    /* 144 x 512 B fp32; OUTS overlay at the end */
#define RED_O  212992    /* float2 [4][144] */
#define LP_O   217600    /* float  [4][144] */
#define RAB_O  219904    /* float  [144] */
#define SCAL_O 220480    /* float[2] */
#define WGS_O  220488    /* float[10] */
#define WB_O   220528    /* float[10] */
#define K2_SMEM 220576

__global__ __launch_bounds__(384, 1) void rnn_fused(
    const float* __restrict__ W_hh,
    const float* __restrict__ ln_g,  const float* __restrict__ ln_b,
    const float* __restrict__ attn_W, const float* __restrict__ attn_b,
    const float* __restrict__ dense_W, const float* __restrict__ dense_b,
    float* __restrict__ out)
{
    extern __shared__ char sm[];
    const uint32_t sb = smem_u32_of(sm);
    const int tid = threadIdx.x, warp = tid >> 5, lane = tid & 31;
    const int g = lane >> 2, q4 = lane & 3;
    const int mgrp = warp >> 2;          // 0..2, rows [48*mgrp, +48)
    const int wnid = warp & 3;           // 0..3, cols [32*wnid, +32)
    const int nw = wnid * 32;
    const int rb = mgrp * 48;
    const int ar = lane & 15;
    const int akbase = ((lane >> 4) << 3);
    const int bnl = lane & 7;
    const int bksel = (((lane >> 3) & 1) << 3);
    const int n0 = blockIdx.x * 144;

    auto cpU = [&](int t) {
#pragma unroll
        for (int j = 0; j < 12; j++) {
            int fi = tid + j * 384;
            int r = fi >> 5, c4 = fi & 31;
            int gr = n0 + r; if (gr > NN - 1) gr = NN - 1;
            CP16(sb + UBUF + fi * 16, g_U + ((size_t)t * NN + gr) * 128 + c4 * 4);
        }
        CP_COMMIT();
    };
    cpU(0);

    conv_weight(W_hh, sm + WHH_HI, sm + WHH_LO, tid, 384);
    if (tid == 0) {
        float s1 = 0.f, s2 = 0.f;
        for (int c = 0; c < 128; c++) {
            s1 += attn_W[c] * ln_g[c];
            s2 += attn_W[c] * ln_b[c];
        }
        ((float*)(sm + SCAL_O))[0] = s1;
        ((float*)(sm + SCAL_O))[1] = s2 + attn_b[0];
    }
    if (tid >= 32 && tid < 32 + CC) {
        int c2 = tid - 32;
        float wg = 0.f, wb = 0.f;
        for (int k = 0; k < 128; k++) {
            float wd = dense_W[c2 * 128 + k];
            wg += wd * ln_g[k];
            wb += wd * ln_b[k];
        }
        ((float*)(sm + WGS_O))[c2] = wg;
        ((float*)(sm + WB_O))[c2] = wb;
    }

    float aw2[4][2];
#pragma unroll
    for (int nt = 0; nt < 4; nt++) {
        int c = nw + nt * 8 + q4 * 2;
        aw2[nt][0] = attn_W[c] * ln_g[c];
        aw2[nt][1] = attn_W[c + 1] * ln_g[c + 1];
    }

    CP_WAIT0();
    __syncthreads();
    const float S1 = ((float*)(sm + SCAL_O))[0];
    const float S2 = ((float*)(sm + SCAL_O))[1];

    // h0 = U[0] (biases folded in k1; no relu): pack into h tiles
#pragma unroll
    for (int mt = 0; mt < 3; mt++)
#pragma unroll
        for (int rh = 0; rh < 2; rh++) {
            int r = rb + mt * 16 + g + rh * 8;
#pragma unroll
            for (int nt = 0; nt < 4; nt++) {
                int c = nw + nt * 8 + q4 * 2;
                float2 u = *(float2*)(sm + UBUF + r * 512 + c * 4);
                uint32_t p0 = packbf(u.x, u.y);
                *(uint32_t*)(sm + H_HI + hswz(r, c)) = p0;
                uint32_t l0 = packbf(u.x - __uint_as_float(p0 << 16),
                                     u.y - __uint_as_float(p0 & 0xffff0000u));
                *(uint32_t*)(sm + H_LO + hswz(r, c)) = l0;
            }
        }
    __syncthreads();

    float P[3][4][4];
#pragma unroll
    for (int mt = 0; mt < 3; mt++)
#pragma unroll
        for (int nt = 0; nt < 4; nt++)
#pragma unroll
            for (int i = 0; i < 4; i++) P[mt][nt][i] = 0.f;
    float rs_s = 0.f, rs_q = 0.f;
    float acc[3][4][4];

    for (int t = 0; t < TT; t++) {
#pragma unroll
        for (int mt = 0; mt < 3; mt++)
#pragma unroll
            for (int nt = 0; nt < 4; nt++)
#pragma unroll
                for (int i = 0; i < 4; i++) acc[mt][nt][i] = 0.f;

        // acc = h @ Whh^T (3 split-bf16 products, n32 per warp)
#pragma unroll
        for (int k0 = 0; k0 < 8; k0++) {
            int bk = k0 * 16 + bksel;
            uint32_t bh[4][2], bl[4][2];
#pragma unroll
            for (int nt = 0; nt < 4; nt++) {
                ldsm2(bh[nt], sb + WHH_HI + hswz(nw + nt * 8 + bnl, bk));
                ldsm2(bl[nt], sb + WHH_LO + hswz(nw + nt * 8 + bnl, bk));
            }
            const int akb = akbase + k0 * 16;
#pragma unroll
            for (int mt = 0; mt < 3; mt++) {
                uint32_t hh[4], hl[4];
                ldsm4(hh, sb + H_HI + hswz(rb + mt * 16 + ar, akb));
                ldsm4(hl, sb + H_LO + hswz(rb + mt * 16 + ar, akb));
#pragma unroll
                for (int nt = 0; nt < 4; nt++) {
                    mma_bf16(acc[mt][nt], hh, bh[nt]);
                    mma_bf16(acc[mt][nt], hh, bl[nt]);
                    mma_bf16(acc[mt][nt], hl, bh[nt]);
                }
            }
        }
        CP_WAIT0();
        __syncthreads();

        // h_{t+1} = relu(acc + U); pack; LN/logit partials
#pragma unroll
        for (int mt = 0; mt < 3; mt++)
#pragma unroll
            for (int rh = 0; rh < 2; rh++) {
                int r = rb + mt * 16 + g + rh * 8;
                float s1 = 0.f, s2 = 0.f, lp = 0.f;
#pragma unroll
                for (int nt = 0; nt < 4; nt++) {
                    int c = nw + nt * 8 + q4 * 2;
                    float2 u = *(float2*)(sm + UBUF + r * 512 + c * 4);
                    float v0 = fmaxf(acc[mt][nt][rh * 2]     + u.x, 0.f);
                    float v1 = fmaxf(acc[mt][nt][rh * 2 + 1] + u.y, 0.f);
                    acc[mt][nt][rh * 2] = v0; acc[mt][nt][rh * 2 + 1] = v1;
                    uint32_t p0 = packbf(v0, v1);
                    *(uint32_t*)(sm + H_HI + hswz(r, c)) = p0;
                    uint32_t l0 = packbf(v0 - __uint_as_float(p0 << 16),
                                         v1 - __uint_as_float(p0 & 0xffff0000u));
                    *(uint32_t*)(sm + H_LO + hswz(r, c)) = l0;
                    s1 += v0 + v1;
                    s2 = fmaf(v0, v0, fmaf(v1, v1, s2));
                    lp = fmaf(v0, aw2[nt][0], fmaf(v1, aw2[nt][1], lp));
                }
                s1 += __shfl_xor_sync(0xffffffffu, s1, 1);
                s1 += __shfl_xor_sync(0xffffffffu, s1, 2);
                s2 += __shfl_xor_sync(0xffffffffu, s2, 1);
                s2 += __shfl_xor_sync(0xffffffffu, s2, 2);
                lp += __shfl_xor_sync(0xffffffffu, lp, 1);
                lp += __shfl_xor_sync(0xffffffffu, lp, 2);
                if (q4 == 0) {
                    *(float2*)(sm + RED_O + (wnid * 144 + r) * 8) = make_float2(s1, s2);
                    ((float*)(sm + LP_O))[wnid * 144 + r] = lp;
                }
            }
        __syncthreads();

        // per-row finalize -> w = exp(l)*rstd (max-free; logits bounded)
        if (tid < 144) {
            float s1 = 0.f, s2 = 0.f, lp = 0.f;
#pragma unroll
            for (int w = 0; w < 4; w++) {
                float2 v = *(float2*)(sm + RED_O + (w * 144 + tid) * 8);
                s1 += v.x; s2 += v.y;
                lp += ((float*)(sm + LP_O))[w * 144 + tid];
            }
            float mu = s1 * (1.0f / 128.0f);
            float var = fmaf(s2, 1.0f / 128.0f, -mu * mu);
            float rstd = rsqrtf(var + 1e-5f);
            float l = fmaf(rstd, lp - mu * S1, S2);
            float e = __expf(l);
            rs_s += e;
            float w = e * rstd;
            rs_q = fmaf(w, mu, rs_q);
            ((float*)(sm + RAB_O))[tid] = w;
        }
        __syncthreads();

        // P += w * h (acc holds h) ; prefetch U[t+1]
#pragma unroll
        for (int mt = 0; mt < 3; mt++)
#pragma unroll
            for (int rh = 0; rh < 2; rh++) {
                int r = rb + mt * 16 + g + rh * 8;
                float w = ((float*)(sm + RAB_O))[r];
#pragma unroll
                for (int nt = 0; nt < 4; nt++) {
                    P[mt][nt][rh * 2]     = fmaf(w, acc[mt][nt][rh * 2],     P[mt][nt][rh * 2]);
                    P[mt][nt][rh * 2 + 1] = fmaf(w, acc[mt][nt][rh * 2 + 1], P[mt][nt][rh * 2 + 1]);
                }
            }
        if (t < TT - 1) cpU(t + 1);
    }

    // ---- final: out = (Σ Wd·γ·P − q·Σ(Wd·γ))/s + Σ(Wd·β) + dense_b ----
    {
        float gl[4][2];
#pragma unroll
        for (int nt = 0; nt < 4; nt++) {
            int c = nw + nt * 8 + q4 * 2;
            gl[nt][0] = ln_g[c];
            gl[nt][1] = ln_g[c + 1];
        }
#pragma unroll
        for (int mt = 0; mt < 3; mt++)
#pragma unroll
            for (int rh = 0; rh < 2; rh++) {
                int r = rb + mt * 16 + g + rh * 8;
#pragma unroll
                for (int c2 = 0; c2 < CC; c2++) {
                    float s = 0.f;
#pragma unroll
                    for (int nt = 0; nt < 4; nt++) {
                        int c = nw + nt * 8 + q4 * 2;
                        s = fmaf(P[mt][nt][rh * 2],     dense_W[c2 * 128 + c] * gl[nt][0], s);
                        s = fmaf(P[mt][nt][rh * 2 + 1], dense_W[c2 * 128 + c + 1] * gl[nt][1], s);
                    }
                    s += __shfl_xor_sync(0xffffffffu, s, 1);
                    s += __shfl_xor_sync(0xffffffffu, s, 2);
                    if (q4 == 0)
                        ((float*)(sm + UBUF))[(wnid * 144 + r) * CC + c2] = s;
                }
            }
    }
    __syncthreads();
    if (tid < 144 && (n0 + tid) < NN) {
        float inv = 1.0f / rs_s;
#pragma unroll
        for (int c2 = 0; c2 < CC; c2++) {
            float tot = 0.f;
#pragma unroll
            for (int w = 0; w < 4; w++)
                tot += ((float*)(sm + UBUF))[(w * 144 + tid) * CC + c2];
            float val = (tot - rs_q * ((float*)(sm + WGS_O))[c2]) * inv
                        + ((float*)(sm + WB_O))[c2] + dense_b[c2];
            out[(n0 + tid) * CC + c2] = val;
        }
    }
}

// ===========================================================================
extern "C" void kernel_launch(void* const* d_in, const int* in_sizes, int n_in,
                              void* d_out, int out_size)
{
    const float* X       = (const float*)d_in[0];
    const float* W_ih    = (const float*)d_in[1];
    const float* W_hh    = (const float*)d_in[2];
    const float* b_ih    = (const float*)d_in[3];
    const float* b_hh    = (const float*)d_in[4];
    const float* ln_g    = (const float*)d_in[5];
    const float* ln_b    = (const float*)d_in[6];
    const float* attn_W  = (const float*)d_in[7];
    const float* attn_b  = (const float*)d_in[8];
    const float* dense_W = (const float*)d_in[9];
    const float* dense_b = (const float*)d_in[10];
    float* out = (float*)d_out;

    cudaFuncSetAttribute(u_gemm, cudaFuncAttributeMaxDynamicSharedMemorySize, K1_SMEM);
    cudaFuncSetAttribute(rnn_fused, cudaFuncAttributeMaxDynamicSharedMemorySize, K2_SMEM);

    u_gemm<<<K1_GRID, 256, K1_SMEM>>>(X, W_ih, b_ih, b_hh);
    rnn_fused<<<(NN + 143) / 144, 384, K2_SMEM>>>(W_hh, ln_g, ln_b, attn_W, attn_b,
                                                  dense_W, dense_b, out);
}